// round 8
// baseline (speedup 1.0000x reference)
#include <cuda_runtime.h>
#include <cuda_fp16.h>
#include <math.h>
#include <stdint.h>

#define LSTEPS 64
#define BDIM   512
#define HDIM   1024
#define SDIM   128
#define ADIM   32
#define NDIM   1024
#define EDIM   1024

#define BH ((size_t)BDIM * HDIM)
#define BS ((size_t)BDIM * SDIM)
#define LBH ((size_t)LSTEPS * BH)
#define LBS ((size_t)LSTEPS * BS)
#define LACT (LSTEPS * BDIM * ADIM)

typedef __half half_t;

// ---------------- scratch: fp16 hi/lo activations ---------------------------
__device__ __align__(16) half_t g_x_h [BDIM * HDIM], g_x_l [BDIM * HDIM];
__device__ __align__(16) half_t g_h_h [2][BDIM * HDIM], g_h_l [2][BDIM * HDIM];
__device__ __align__(16) half_t g_pe_h[BDIM * NDIM], g_pe_l[BDIM * NDIM];
__device__ __align__(16) half_t g_qe_h[BDIM * NDIM], g_qe_l[BDIM * NDIM];
__device__ __align__(16) half_t g_ob_h[BDIM * EDIM], g_ob_l[BDIM * EDIM];
__device__ __align__(16) half_t g_sp_h[BDIM * SDIM], g_sp_l[BDIM * SDIM];
__device__ __align__(16) half_t g_act_h[LACT], g_act_l[LACT];

// ---------------- scratch: converted weights (fp16) -------------------------
#define SZ_WSA (HDIM * (SDIM + ADIM))
#define SZ_WIH (3 * HDIM * HDIM)
#define SZ_WEP (NDIM * HDIM)
#define SZ_WPR (2 * SDIM * NDIM)
#define SZ_WEQ (NDIM * (HDIM + EDIM))

__device__ __align__(16) half_t g_Wsa[SZ_WSA];
__device__ __align__(16) half_t g_Wih[SZ_WIH];
__device__ __align__(16) half_t g_Whh[SZ_WIH];
__device__ __align__(16) half_t g_Wep[SZ_WEP];
__device__ __align__(16) half_t g_Wpr[SZ_WPR];   // row-interleaved mean/std
__device__ __align__(16) half_t g_Weq[SZ_WEQ];
__device__ __align__(16) half_t g_Wpo[SZ_WPR];   // row-interleaved mean/std

// ------------------------------- helpers ------------------------------------
__device__ __forceinline__ float sigmoidf_(float x) { return 1.0f / (1.0f + __expf(-x)); }
__device__ __forceinline__ float tanhf_(float x)    { return 1.0f - 2.0f / (__expf(2.0f * x) + 1.0f); }
__device__ __forceinline__ float softplusf_(float x) {
    return fmaxf(x, 0.0f) + log1pf(__expf(-fabsf(x)));
}
__device__ __forceinline__ uint32_t pack_h2(half_t a, half_t b) {
    __half2 t(a, b);
    return *reinterpret_cast<uint32_t*>(&t);
}
__device__ __forceinline__ void split_h(float v, half_t& h, half_t& l) {
    h = __float2half_rn(v);
    l = __float2half_rn(v - __half2float(h));
}
__device__ __forceinline__ void split_store4(float4 v, half_t* hdst, half_t* ldst, size_t idx4) {
    half_t h0, h1, h2, h3, l0, l1, l2, l3;
    split_h(v.x, h0, l0); split_h(v.y, h1, l1);
    split_h(v.z, h2, l2); split_h(v.w, h3, l3);
    reinterpret_cast<uint2*>(hdst)[idx4] = make_uint2(pack_h2(h0, h1), pack_h2(h2, h3));
    reinterpret_cast<uint2*>(ldst)[idx4] = make_uint2(pack_h2(l0, l1), pack_h2(l2, l3));
}
__device__ __forceinline__ void ldsm4(uint32_t* r, uint32_t addr) {
    asm volatile("ldmatrix.sync.aligned.m8n8.x4.shared.b16 {%0,%1,%2,%3}, [%4];"
                 : "=r"(r[0]), "=r"(r[1]), "=r"(r[2]), "=r"(r[3]) : "r"(addr));
}
__device__ __forceinline__ void mma_f16(float* c, const uint32_t* a, uint32_t b0, uint32_t b1) {
    asm volatile("mma.sync.aligned.m16n8k16.row.col.f32.f16.f16.f32 "
                 "{%0,%1,%2,%3}, {%4,%5,%6,%7}, {%8,%9}, {%0,%1,%2,%3};"
                 : "+f"(c[0]), "+f"(c[1]), "+f"(c[2]), "+f"(c[3])
                 : "r"(a[0]), "r"(a[1]), "r"(a[2]), "r"(a[3]), "r"(b0), "r"(b1));
}
__device__ __forceinline__ void cp16(uint32_t dst, const void* src) {
    asm volatile("cp.async.cg.shared.global [%0], [%1], 16;" :: "r"(dst), "l"(src));
}
__device__ __forceinline__ void cp_commit() {
    asm volatile("cp.async.commit_group;" ::: "memory");
}
__device__ __forceinline__ void cp_wait1() {
    asm volatile("cp.async.wait_group 1;" ::: "memory");
}

// -------------------- weight conversion kernels -----------------------------
__global__ void convert2_kernel(const float* __restrict__ a, half_t* __restrict__ oa,
                                const float* __restrict__ b, half_t* __restrict__ ob, int n4)
{
    int i = blockIdx.x * blockDim.x + threadIdx.x;
    if (i >= n4) return;
    const float* s = blockIdx.y ? b : a;
    half_t* d = blockIdx.y ? ob : oa;
    float4 v = reinterpret_cast<const float4*>(s)[i];
    reinterpret_cast<uint2*>(d)[i] =
        make_uint2(pack_h2(__float2half_rn(v.x), __float2half_rn(v.y)),
                   pack_h2(__float2half_rn(v.z), __float2half_rn(v.w)));
}

__global__ void convert3_kernel(const float* __restrict__ a, half_t* __restrict__ oa, int na4,
                                const float* __restrict__ b, half_t* __restrict__ ob, int nb4,
                                const float* __restrict__ c, half_t* __restrict__ oc, int nc4)
{
    int i = blockIdx.x * blockDim.x + threadIdx.x;
    const float* s; half_t* d; int n4;
    if (blockIdx.y == 0)      { s = a; d = oa; n4 = na4; }
    else if (blockIdx.y == 1) { s = b; d = ob; n4 = nb4; }
    else                      { s = c; d = oc; n4 = nc4; }
    if (i >= n4) return;
    float4 v = reinterpret_cast<const float4*>(s)[i];
    reinterpret_cast<uint2*>(d)[i] =
        make_uint2(pack_h2(__float2half_rn(v.x), __float2half_rn(v.y)),
                   pack_h2(__float2half_rn(v.z), __float2half_rn(v.w)));
}

__global__ void convert_ilv2_kernel(const float* __restrict__ a, half_t* __restrict__ oa,
                                    const float* __restrict__ b, half_t* __restrict__ ob)
{
    const int K4 = NDIM / 4;
    int idx = blockIdx.x * blockDim.x + threadIdx.x;
    if (idx >= 2 * SDIM * K4) return;
    const float* s = blockIdx.y ? b : a;
    half_t* d = blockIdx.y ? ob : oa;
    int r = idx / K4, k4 = idx % K4;
    int sr = (r & 1) ? (r >> 1) + SDIM : (r >> 1);
    float4 v = *reinterpret_cast<const float4*>(s + (size_t)sr * NDIM + k4 * 4);
    reinterpret_cast<uint2*>(d)[idx] =
        make_uint2(pack_h2(__float2half_rn(v.x), __float2half_rn(v.y)),
                   pack_h2(__float2half_rn(v.z), __float2half_rn(v.w)));
}

__global__ void init_kernel(const float* __restrict__ prev_hidden,
                            const float* __restrict__ prev_state,
                            const float* __restrict__ nt0,
                            const float* __restrict__ actions,
                            half_t* __restrict__ hh, half_t* __restrict__ hl,
                            half_t* __restrict__ sph, half_t* __restrict__ spl,
                            half_t* __restrict__ ah, half_t* __restrict__ al)
{
    const int N1 = (int)(BH / 4), N2 = (int)(BS / 4), N3 = LACT / 4;
    int idx = blockIdx.x * blockDim.x + threadIdx.x;
    if (idx < N1) {
        float4 v = reinterpret_cast<const float4*>(prev_hidden)[idx];
        split_store4(v, hh, hl, idx);
    } else if (idx < N1 + N2) {
        int j = idx - N1;
        float4 v = reinterpret_cast<const float4*>(prev_state)[j];
        float s = nt0[(j * 4) / SDIM];
        v.x *= s; v.y *= s; v.z *= s; v.w *= s;
        split_store4(v, sph, spl, j);
    } else if (idx < N1 + N2 + N3) {
        int j = idx - N1 - N2;
        float4 v = reinterpret_cast<const float4*>(actions)[j];
        split_store4(v, ah, al, j);
    }
}

// ------------------------------ GEMM args -----------------------------------
struct G {
    const half_t *Ah, *Al;
    const half_t *A2h, *A2l;
    const half_t* W;
    const float* bias;
    float* C; float* C2;
    const float* noise;
    float* S;
    half_t *Ch, *Cl;
    half_t *Sh, *Sl;
    const float* ntNext;
    int K, kSplit, sA, sA2;
};

// -------- fp16 2-pass tensor-core GEMM, cp.async 3-stage (C = A @ W^T) ------
// EPI: 1 bias+relu->fp16 hi/lo; 2 interleaved heads
template<int BM, int BN, int WM, int WN, int NWARPS, int EPI>
__global__ __launch_bounds__(NWARPS * 32, 1)
void gemm_tc(G g0, G g1, int N)
{
    constexpr int THREADS = NWARPS * 32;
    constexpr int BK  = 32;
    constexpr int LDS = BK + 8;
    constexpr int WTM = BM / WM;
    constexpr int WTN = BN / WN;
    constexpr int FM  = WTM / 16;
    constexpr int FN  = WTN / 8;
    static_assert(FN % 2 == 0, "");
    static_assert(WM * WN == NWARPS, "");
    constexpr int ACH = BM * 4;
    constexpr int BCH = BN * 4;
    constexpr int CH_TOT = 2 * ACH + BCH;
    constexpr int ABLK_B = BM * LDS * 2;
    constexpr int BBLK_B = BN * LDS * 2;
    constexpr int STG_B  = 2 * ABLK_B + BBLK_B;

    extern __shared__ __align__(16) char dynsmem[];
    const uint32_t sbase = (uint32_t)__cvta_generic_to_shared(dynsmem);

    const G g = (blockIdx.z == 0) ? g0 : g1;
    const int K = g.K;
    const int tid  = threadIdx.x;
    const int wid  = tid >> 5;
    const int lane = tid & 31;
    const int wm = wid % WM, wn = wid / WM;
    const int bm = blockIdx.y * BM, bn = blockIdx.x * BN;

    float acc[FM][FN][4];
#pragma unroll
    for (int i = 0; i < FM; i++)
#pragma unroll
        for (int j = 0; j < FN; j++)
#pragma unroll
            for (int q = 0; q < 4; q++) acc[i][j][q] = 0.0f;

    auto loadStage = [&](int ck, int buf) {
        const int ko = ck * BK;
        const half_t *ah, *al; int kb, sa;
        if (ko < g.kSplit) { ah = g.Ah;  al = g.Al;  kb = ko;             sa = g.sA;  }
        else               { ah = g.A2h; al = g.A2l; kb = ko - g.kSplit;  sa = g.sA2; }
        const uint32_t sb = sbase + (uint32_t)buf * STG_B;
#pragma unroll 2
        for (int i = tid; i < CH_TOT; i += THREADS) {
            const half_t* src; uint32_t dst;
            if (i < ACH) {
                int r = i >> 2, c = i & 3;
                src = ah + (size_t)(bm + r) * sa + kb + c * 8;
                dst = sb + (uint32_t)(r * LDS + c * 8) * 2;
            } else if (i < 2 * ACH) {
                int j = i - ACH;
                int r = j >> 2, c = j & 3;
                src = al + (size_t)(bm + r) * sa + kb + c * 8;
                dst = sb + ABLK_B + (uint32_t)(r * LDS + c * 8) * 2;
            } else {
                int j = i - 2 * ACH;
                int r = j >> 2, c = j & 3;
                src = g.W + (size_t)(bn + r) * K + ko + c * 8;
                dst = sb + 2 * ABLK_B + (uint32_t)(r * LDS + c * 8) * 2;
            }
            cp16(dst, src);
        }
    };

    const int kT = K / BK;
    loadStage(0, 0); cp_commit();
    loadStage(1, 1); cp_commit();

    int cbuf = 0, lbuf = 2;
    for (int kt = 0; kt < kT; kt++) {
        cp_wait1();
        __syncthreads();
        if (kt + 2 < kT) loadStage(kt + 2, lbuf);
        cp_commit();

        const uint32_t aBaseH = sbase + (uint32_t)cbuf * STG_B;
        const uint32_t aBaseL = aBaseH + ABLK_B;
        const uint32_t bBase  = aBaseH + 2 * ABLK_B;

#pragma unroll
        for (int k16 = 0; k16 < 2; k16++) {
            uint32_t afh[FM][4], afl[FM][4];
            const int acol = k16 * 16 + ((lane >> 4) << 3);
#pragma unroll
            for (int fm = 0; fm < FM; fm++) {
                const int arow = wm * WTM + fm * 16 + (lane & 15);
                const uint32_t aoff = (uint32_t)(arow * LDS + acol) * 2u;
                ldsm4(afh[fm], aBaseH + aoff);
                ldsm4(afl[fm], aBaseL + aoff);
            }
            const int brlane = ((lane >> 4) << 3) + (lane & 7);
            const int bcol   = k16 * 16 + (((lane >> 3) & 1) << 3);
#pragma unroll
            for (int fn2 = 0; fn2 < FN / 2; fn2++) {
                const int brow = wn * WTN + fn2 * 16 + brlane;
                const uint32_t boff = (uint32_t)(brow * LDS + bcol) * 2u;
                uint32_t bh[4];
                ldsm4(bh, bBase + boff);
#pragma unroll
                for (int fm = 0; fm < FM; fm++) {
                    float* c0 = acc[fm][2 * fn2];
                    float* c1 = acc[fm][2 * fn2 + 1];
                    mma_f16(c0, afh[fm], bh[0], bh[1]);
                    mma_f16(c0, afl[fm], bh[0], bh[1]);
                    mma_f16(c1, afh[fm], bh[2], bh[3]);
                    mma_f16(c1, afl[fm], bh[2], bh[3]);
                }
            }
        }
        __syncthreads();
        cbuf = (cbuf == 2) ? 0 : cbuf + 1;
        lbuf = (lbuf == 2) ? 0 : lbuf + 1;
    }

    const int gid = lane >> 2, tig = lane & 3;
#pragma unroll
    for (int fm = 0; fm < FM; fm++) {
        const int m0 = bm + wm * WTM + fm * 16 + gid;
#pragma unroll
        for (int fn = 0; fn < FN; fn++) {
            const int n0 = bn + wn * WTN + fn * 8 + tig * 2;
            if (EPI == 2) {
                const int i = n0 >> 1;
                const float bm_ = g.bias[i], bs_ = g.bias[i + SDIM];
                float me0 = acc[fm][fn][0] + bm_;
                float sd0 = softplusf_(acc[fm][fn][1] + bs_) + 0.1f;
                float me1 = acc[fm][fn][2] + bm_;
                float sd1 = softplusf_(acc[fm][fn][3] + bs_) + 0.1f;
                const size_t o0 = (size_t)m0 * SDIM + i;
                const size_t o1 = (size_t)(m0 + 8) * SDIM + i;
                g.C [o0] = me0;  g.C [o1] = me1;
                g.C2[o0] = sd0;  g.C2[o1] = sd1;
                float s0 = fmaf(sd0, g.noise[o0], me0);
                float s1 = fmaf(sd1, g.noise[o1], me1);
                g.S[o0] = s0;  g.S[o1] = s1;
                if (g.Sh) {
                    float sc0 = s0 * g.ntNext[m0];
                    float sc1 = s1 * g.ntNext[m0 + 8];
                    half_t h, l;
                    split_h(sc0, h, l); g.Sh[o0] = h; g.Sl[o0] = l;
                    split_h(sc1, h, l); g.Sh[o1] = h; g.Sl[o1] = l;
                }
            } else {
                const float b0 = g.bias[n0], b1 = g.bias[n0 + 1];
                float v00 = fmaxf(acc[fm][fn][0] + b0, 0.0f);
                float v01 = fmaxf(acc[fm][fn][1] + b1, 0.0f);
                float v10 = fmaxf(acc[fm][fn][2] + b0, 0.0f);
                float v11 = fmaxf(acc[fm][fn][3] + b1, 0.0f);
                half_t h0, l0, h1, l1;
                split_h(v00, h0, l0); split_h(v01, h1, l1);
                *reinterpret_cast<uint32_t*>(g.Ch + (size_t)m0 * N + n0) = pack_h2(h0, h1);
                *reinterpret_cast<uint32_t*>(g.Cl + (size_t)m0 * N + n0) = pack_h2(l0, l1);
                split_h(v10, h0, l0); split_h(v11, h1, l1);
                *reinterpret_cast<uint32_t*>(g.Ch + (size_t)(m0 + 8) * N + n0) = pack_h2(h0, h1);
                *reinterpret_cast<uint32_t*>(g.Cl + (size_t)(m0 + 8) * N + n0) = pack_h2(l0, l1);
            }
        }
    }
}

// ============ fused GRU GEMM: rz (K=2048) + in/hn (K-phased) ================
// grid (16 j-tiles, 8 m-tiles); BM=64, BN=64; 8 warps (WM=2, WN=4)
__global__ __launch_bounds__(256, 1)
void gru_fused(const half_t* __restrict__ xh, const half_t* __restrict__ xl,
               const half_t* __restrict__ hh, const half_t* __restrict__ hl,
               const half_t* __restrict__ Wih, const half_t* __restrict__ Whh,
               const float* __restrict__ b_ih, const float* __restrict__ b_hh,
               const float* __restrict__ hprev, float* __restrict__ hnew,
               half_t* __restrict__ hho, half_t* __restrict__ hlo,
               const float* __restrict__ obs_t,
               half_t* __restrict__ oh, half_t* __restrict__ ol)
{
    constexpr int BM = 64, BN = 64, LDS = 40;
    constexpr int ABLK_B = BM * LDS * 2;   // 5120
    constexpr int BBLK_B = BN * LDS * 2;   // 5120
    constexpr int STG_B  = 2 * ABLK_B + 3 * BBLK_B;  // 25600
    constexpr int CH_TOT = 2 * BM * 4 + 3 * BN * 4;  // 1280

    extern __shared__ __align__(16) char dynsmem[];
    const uint32_t sbase = (uint32_t)__cvta_generic_to_shared(dynsmem);

    const int tid  = threadIdx.x;
    const int wid  = tid >> 5;
    const int lane = tid & 31;
    const int wm = wid & 1, wn = wid >> 1;      // WM=2, WN=4
    const int bm = blockIdx.y * BM, bn = blockIdx.x * BN;

    // acc[set][fm][fn][4]: set 0=r, 1=z, 2=in, 3=hn;  FM=2, FN=2
    float acc[4][2][2][4];
#pragma unroll
    for (int s = 0; s < 4; s++)
#pragma unroll
        for (int i = 0; i < 2; i++)
#pragma unroll
            for (int j = 0; j < 2; j++)
#pragma unroll
                for (int q = 0; q < 4; q++) acc[s][i][j][q] = 0.0f;

    auto loadStage = [&](int ck, int buf) {
        const int ko = ck * 32;
        const bool xp = (ko < HDIM);
        const half_t* Ah = xp ? xh : hh;
        const half_t* Al = xp ? xl : hl;
        const half_t* W  = xp ? Wih : Whh;
        const int kb = xp ? ko : ko - HDIM;
        const uint32_t sb = sbase + (uint32_t)buf * STG_B;
#pragma unroll 2
        for (int i = tid; i < CH_TOT; i += 256) {
            const half_t* src; uint32_t dst;
            if (i < 512) {
                int part = i >> 8;          // 0 hi, 1 lo
                int j = i & 255; int r = j >> 2, c = j & 3;
                src = (part ? Al : Ah) + (size_t)(bm + r) * HDIM + kb + c * 8;
                dst = sb + (uint32_t)part * ABLK_B + (uint32_t)(r * LDS + c * 8) * 2;
            } else {
                int j = i - 512;
                int gate = j >> 8;          // 0=r, 1=z, 2=n
                int jj = j & 255; int r = jj >> 2, c = jj & 3;
                src = W + (size_t)(gate * HDIM + bn + r) * HDIM + kb + c * 8;
                dst = sb + 2 * ABLK_B + (uint32_t)gate * BBLK_B
                         + (uint32_t)(r * LDS + c * 8) * 2;
            }
            cp16(dst, src);
        }
    };

    const int kT = 2 * HDIM / 32;    // 64
    loadStage(0, 0); cp_commit();
    loadStage(1, 1); cp_commit();

    int cbuf = 0, lbuf = 2;
    for (int kt = 0; kt < kT; kt++) {
        cp_wait1();
        __syncthreads();
        if (kt + 2 < kT) loadStage(kt + 2, lbuf);
        cp_commit();

        const bool xp = (kt < kT / 2);
        const uint32_t aBaseH = sbase + (uint32_t)cbuf * STG_B;
        const uint32_t aBaseL = aBaseH + ABLK_B;
        const uint32_t bBase  = aBaseH + 2 * ABLK_B;

#pragma unroll
        for (int k16 = 0; k16 < 2; k16++) {
            uint32_t afh[2][4], afl[2][4];
            const int acol = k16 * 16 + ((lane >> 4) << 3);
#pragma unroll
            for (int fm = 0; fm < 2; fm++) {
                const int arow = wm * 32 + fm * 16 + (lane & 15);
                const uint32_t aoff = (uint32_t)(arow * LDS + acol) * 2u;
                ldsm4(afh[fm], aBaseH + aoff);
                ldsm4(afl[fm], aBaseL + aoff);
            }
            const int brlane = ((lane >> 4) << 3) + (lane & 7);
            const int bcol   = k16 * 16 + (((lane >> 3) & 1) << 3);
            const int brow   = wn * 16 + brlane;
            const uint32_t boff = (uint32_t)(brow * LDS + bcol) * 2u;
#pragma unroll
            for (int gate = 0; gate < 3; gate++) {
                uint32_t bfr[4];
                ldsm4(bfr, bBase + (uint32_t)gate * BBLK_B + boff);
                const int s = (gate < 2) ? gate : (xp ? 2 : 3);
#pragma unroll
                for (int fm = 0; fm < 2; fm++) {
                    float* c0 = acc[s][fm][0];
                    float* c1 = acc[s][fm][1];
                    mma_f16(c0, afh[fm], bfr[0], bfr[1]);
                    mma_f16(c0, afl[fm], bfr[0], bfr[1]);
                    mma_f16(c1, afh[fm], bfr[2], bfr[3]);
                    mma_f16(c1, afl[fm], bfr[2], bfr[3]);
                }
            }
        }
        __syncthreads();
        cbuf = (cbuf == 2) ? 0 : cbuf + 1;
        lbuf = (lbuf == 2) ? 0 : lbuf + 1;
    }

    // ---- gate epilogue -> hnew fp32 + hi/lo split --------------------------
    const int gid = lane >> 2, tig = lane & 3;
#pragma unroll
    for (int fm = 0; fm < 2; fm++) {
        const int m0 = bm + wm * 32 + fm * 16 + gid;
#pragma unroll
        for (int fn = 0; fn < 2; fn++) {
            const int n0 = bn + wn * 16 + fn * 8 + tig * 2;
            const float br0 = b_ih[n0] + b_hh[n0];
            const float br1 = b_ih[n0 + 1] + b_hh[n0 + 1];
            const float bz0 = b_ih[n0 + HDIM] + b_hh[n0 + HDIM];
            const float bz1 = b_ih[n0 + 1 + HDIM] + b_hh[n0 + 1 + HDIM];
            const float bi0 = b_ih[n0 + 2 * HDIM], bi1 = b_ih[n0 + 1 + 2 * HDIM];
            const float bh0 = b_hh[n0 + 2 * HDIM], bh1 = b_hh[n0 + 1 + 2 * HDIM];
#pragma unroll
            for (int rs = 0; rs < 2; rs++) {
                const int m = m0 + rs * 8;
                const int q = rs * 2;
                float2 hp = *reinterpret_cast<const float2*>(hprev + (size_t)m * HDIM + n0);
                float r0 = sigmoidf_(acc[0][fm][fn][q]     + br0);
                float r1 = sigmoidf_(acc[0][fm][fn][q + 1] + br1);
                float z0 = sigmoidf_(acc[1][fm][fn][q]     + bz0);
                float z1 = sigmoidf_(acc[1][fm][fn][q + 1] + bz1);
                float n0v = tanhf_(acc[2][fm][fn][q]     + bi0 + r0 * (acc[3][fm][fn][q]     + bh0));
                float n1v = tanhf_(acc[2][fm][fn][q + 1] + bi1 + r1 * (acc[3][fm][fn][q + 1] + bh1));
                float v0 = (1.0f - z0) * n0v + z0 * hp.x;
                float v1 = (1.0f - z1) * n1v + z1 * hp.y;
                *reinterpret_cast<float2*>(hnew + (size_t)m * HDIM + n0) = make_float2(v0, v1);
                half_t h, l;
                split_h(v0, h, l);
                half_t h2, l2;
                split_h(v1, h2, l2);
                *reinterpret_cast<uint32_t*>(hho + (size_t)m * HDIM + n0) = pack_h2(h, h2);
                *reinterpret_cast<uint32_t*>(hlo + (size_t)m * HDIM + n0) = pack_h2(l, l2);
            }
        }
    }

    // ---- obs tile conversion (this CTA's 64x64 patch) ----------------------
    for (int i = tid; i < BM * (BN / 4); i += 256) {
        int r = i / (BN / 4), c4 = i % (BN / 4);
        size_t off4 = ((size_t)(bm + r) * EDIM + bn) / 4 + c4;
        float4 v = reinterpret_cast<const float4*>(obs_t)[off4];
        split_store4(v, oh, ol, off4);
    }
}

// ------------------------------- launch --------------------------------------
extern "C" void kernel_launch(void* const* d_in, const int* in_sizes, int n_in,
                              void* d_out, int out_size)
{
    (void)in_sizes; (void)n_in; (void)out_size;
    const float* prev_hidden = (const float*)d_in[0];
    const float* prev_state  = (const float*)d_in[1];
    const float* actions     = (const float*)d_in[2];
    const float* obs         = (const float*)d_in[3];
    const float* non_terms   = (const float*)d_in[4];
    const float* prior_noise = (const float*)d_in[5];
    const float* post_noise  = (const float*)d_in[6];
    const float* W_sa = (const float*)d_in[7];
    const float* b_sa = (const float*)d_in[8];
    const float* W_ih = (const float*)d_in[9];
    const float* W_hh = (const float*)d_in[10];
    const float* b_ih = (const float*)d_in[11];
    const float* b_hh = (const float*)d_in[12];
    const float* W_ep = (const float*)d_in[13];
    const float* b_ep = (const float*)d_in[14];
    const float* W_pr = (const float*)d_in[15];
    const float* b_pr = (const float*)d_in[16];
    const float* W_eq = (const float*)d_in[17];
    const float* b_eq = (const float*)d_in[18];
    const float* W_po = (const float*)d_in[19];
    const float* b_po = (const float*)d_in[20];

    float* out = (float*)d_out;
    const size_t off_pm     = LBH;
    const size_t off_ps     = LBH + 1 * LBS;
    const size_t off_sprior = LBH + 2 * LBS;
    const size_t off_qm     = LBH + 3 * LBS;
    const size_t off_qs     = LBH + 4 * LBS;
    const size_t off_spost  = LBH + 5 * LBS;

    half_t *x_h, *x_l, *pe_h, *pe_l, *qe_h, *qe_l, *ob_h, *ob_l;
    half_t *sp_h, *sp_l, *act_h, *act_l;
    half_t *h_h0, *h_l0, *h_h1, *h_l1;
    cudaGetSymbolAddress((void**)&x_h,  g_x_h);  cudaGetSymbolAddress((void**)&x_l,  g_x_l);
    cudaGetSymbolAddress((void**)&pe_h, g_pe_h); cudaGetSymbolAddress((void**)&pe_l, g_pe_l);
    cudaGetSymbolAddress((void**)&qe_h, g_qe_h); cudaGetSymbolAddress((void**)&qe_l, g_qe_l);
    cudaGetSymbolAddress((void**)&ob_h, g_ob_h); cudaGetSymbolAddress((void**)&ob_l, g_ob_l);
    cudaGetSymbolAddress((void**)&sp_h, g_sp_h); cudaGetSymbolAddress((void**)&sp_l, g_sp_l);
    cudaGetSymbolAddress((void**)&act_h, g_act_h); cudaGetSymbolAddress((void**)&act_l, g_act_l);
    cudaGetSymbolAddress((void**)&h_h0, g_h_h);  cudaGetSymbolAddress((void**)&h_l0, g_h_l);
    h_h1 = h_h0 + BH; h_l1 = h_l0 + BH;

    half_t *Wsa, *Wih, *Whh, *Wep, *Wpr, *Weq, *Wpo;
    cudaGetSymbolAddress((void**)&Wsa, g_Wsa);
    cudaGetSymbolAddress((void**)&Wih, g_Wih);
    cudaGetSymbolAddress((void**)&Whh, g_Whh);
    cudaGetSymbolAddress((void**)&Wep, g_Wep);
    cudaGetSymbolAddress((void**)&Wpr, g_Wpr);
    cudaGetSymbolAddress((void**)&Weq, g_Weq);
    cudaGetSymbolAddress((void**)&Wpo, g_Wpo);

    // ---- preamble ----
    convert2_kernel<<<dim3(SZ_WIH / 4 / 256, 2, 1), 256>>>(W_ih, Wih, W_hh, Whh, SZ_WIH / 4);
    convert3_kernel<<<dim3(SZ_WEQ / 4 / 256, 3, 1), 256>>>(
        W_sa, Wsa, SZ_WSA / 4, W_ep, Wep, SZ_WEP / 4, W_eq, Weq, SZ_WEQ / 4);
    convert_ilv2_kernel<<<dim3((2 * SDIM * (NDIM / 4) + 255) / 256, 2, 1), 256>>>(
        W_pr, Wpr, W_po, Wpo);
    {
        int tot = (int)(BH / 4 + BS / 4 + LACT / 4);
        init_kernel<<<(tot + 255) / 256, 256>>>(
            prev_hidden, prev_state, non_terms, actions,
            h_h0, h_l0, sp_h, sp_l, act_h, act_l);
    }

    // ---- dynamic smem ----
    const int SM_PQ    = 3 * (2 * 64 * 40 + 128 * 40) * 2;   // 61440
    const int SM_X     = 3 * (2 * 64 * 40 + 64 * 40) * 2;    // 46080
    const int SM_HEAD  = 3 * (2 * 32 * 40 + 64 * 40) * 2;    // 30720
    const int SM_FUSED = 3 * 25600;                          // 76800

    cudaFuncSetAttribute((const void*)gemm_tc<64, 128, 2, 4, 8, 1>,
                         cudaFuncAttributeMaxDynamicSharedMemorySize, SM_PQ);
    cudaFuncSetAttribute((const void*)gemm_tc<64, 64, 2, 4, 8, 1>,
                         cudaFuncAttributeMaxDynamicSharedMemorySize, SM_X);
    cudaFuncSetAttribute((const void*)gemm_tc<32, 64, 1, 4, 4, 2>,
                         cudaFuncAttributeMaxDynamicSharedMemorySize, SM_HEAD);
    cudaFuncSetAttribute((const void*)gru_fused,
                         cudaFuncAttributeMaxDynamicSharedMemorySize, SM_FUSED);

    const int KSA = SDIM + ADIM;
    const int KHE = HDIM + EDIM;

    for (int t = 0; t < LSTEPS; t++) {
        const float* hprev = (t == 0) ? prev_hidden : out + (size_t)(t - 1) * BH;
        float* hnew = out + (size_t)t * BH;
        const float* obs_t = obs + (size_t)t * BDIM * EDIM;
        const half_t* act_ht = act_h + (size_t)t * BDIM * ADIM;
        const half_t* act_lt = act_l + (size_t)t * BDIM * ADIM;
        const float* ntNext = non_terms + (size_t)((t + 1 < LSTEPS) ? t + 1 : t) * BDIM;
        // h ping-pong: read rbuf (h_{t-1}), write wbuf (h_t)
        half_t* h_rh = (t & 1) ? h_h1 : h_h0;
        half_t* h_rl = (t & 1) ? h_l1 : h_l0;
        half_t* h_wh = (t & 1) ? h_h0 : h_h1;
        half_t* h_wl = (t & 1) ? h_l0 : h_l1;

        // 1) x = relu([spost*nt, a] @ Wsa^T + b_sa) -> fp16 hi/lo
        {
            G a{sp_h, sp_l, act_ht, act_lt, Wsa, b_sa,
                nullptr, nullptr, nullptr, nullptr, x_h, x_l,
                nullptr, nullptr, nullptr, KSA, SDIM, SDIM, ADIM};
            gemm_tc<64, 64, 2, 4, 8, 1><<<dim3(HDIM / 64, BDIM / 64, 1), 256, SM_X>>>(
                a, a, HDIM);
        }
        // 2) fused GRU GEMM + gates + obs conversion
        gru_fused<<<dim3(HDIM / 64, BDIM / 64, 1), 256, SM_FUSED>>>(
            x_h, x_l, h_rh, h_rl, Wih, Whh, b_ih, b_hh,
            hprev, hnew, h_wh, h_wl, obs_t, ob_h, ob_l);

        // 3) pe = relu(h @ Wep^T + b_ep) ; qe = relu([h,obs] @ Weq^T + b_eq)
        {
            G a0{h_wh, h_wl, h_wh, h_wl, Wep, b_ep, nullptr, nullptr, nullptr, nullptr,
                 pe_h, pe_l, nullptr, nullptr, nullptr, HDIM, HDIM, HDIM, HDIM};
            G a1{h_wh, h_wl, ob_h, ob_l, Weq, b_eq, nullptr, nullptr, nullptr, nullptr,
                 qe_h, qe_l, nullptr, nullptr, nullptr, KHE, HDIM, HDIM, EDIM};
            gemm_tc<64, 128, 2, 4, 8, 1><<<dim3(NDIM / 128, BDIM / 64, 2), 256, SM_PQ>>>(
                a0, a1, NDIM);
        }
        // 4) heads + reparameterized states (fused)
        float* pm_o = out + off_pm + (size_t)t * BS;
        float* ps_o = out + off_ps + (size_t)t * BS;
        float* qm_o = out + off_qm + (size_t)t * BS;
        float* qs_o = out + off_qs + (size_t)t * BS;
        {
            G a0{pe_h, pe_l, pe_h, pe_l, Wpr, b_pr, pm_o, ps_o,
                 prior_noise + (size_t)t * BS, out + off_sprior + (size_t)t * BS,
                 nullptr, nullptr, nullptr, nullptr, nullptr, NDIM, NDIM, NDIM, NDIM};
            G a1{qe_h, qe_l, qe_h, qe_l, Wpo, b_po, qm_o, qs_o,
                 post_noise + (size_t)t * BS, out + off_spost + (size_t)t * BS,
                 nullptr, nullptr, sp_h, sp_l, ntNext, NDIM, NDIM, NDIM, NDIM};
            gemm_tc<32, 64, 1, 4, 4, 2><<<dim3(2 * SDIM / 64, BDIM / 32, 2), 128, SM_HEAD>>>(
                a0, a1, 2 * SDIM);
        }
    }
}

// round 9
// speedup vs baseline: 1.2316x; 1.2316x over previous
#include <cuda_runtime.h>
#include <cuda_fp16.h>
#include <math.h>
#include <stdint.h>

#define LSTEPS 64
#define BDIM   512
#define HDIM   1024
#define SDIM   128
#define ADIM   32
#define NDIM   1024
#define EDIM   1024

#define BH ((size_t)BDIM * HDIM)
#define BS ((size_t)BDIM * SDIM)
#define LBH ((size_t)LSTEPS * BH)
#define LBS ((size_t)LSTEPS * BS)
#define LACT (LSTEPS * BDIM * ADIM)
#define LOBS ((size_t)LSTEPS * BDIM * EDIM)

typedef __half half_t;

// ---------------- scratch: fp32 ---------------------------------------------
__device__ __align__(16) float g_gi[BDIM * 3 * HDIM];
__device__ __align__(16) float g_gh[BDIM * 3 * HDIM];
__device__ __align__(16) float g_qp[LOBS];            // qe obs-partial (+b_eq), 128MB

// ---------------- scratch: fp16 hi/lo activations ---------------------------
__device__ __align__(16) half_t g_x_h [BDIM * HDIM], g_x_l [BDIM * HDIM];
__device__ __align__(16) half_t g_h_h [BDIM * HDIM], g_h_l [BDIM * HDIM];
__device__ __align__(16) half_t g_pe_h[BDIM * NDIM], g_pe_l[BDIM * NDIM];
__device__ __align__(16) half_t g_qe_h[BDIM * NDIM], g_qe_l[BDIM * NDIM];
__device__ __align__(16) half_t g_sp_h[BDIM * SDIM], g_sp_l[BDIM * SDIM];
__device__ __align__(16) half_t g_act_h[LACT], g_act_l[LACT];
__device__ __align__(16) half_t g_ob_h[LOBS], g_ob_l[LOBS];   // all steps

// ---------------- scratch: converted weights (fp16) -------------------------
#define SZ_WSA (HDIM * (SDIM + ADIM))
#define SZ_WIH (3 * HDIM * HDIM)
#define SZ_WEP (NDIM * HDIM)
#define SZ_WPR (2 * SDIM * NDIM)

__device__ __align__(16) half_t g_Wsa[SZ_WSA];
__device__ __align__(16) half_t g_Wih[SZ_WIH];
__device__ __align__(16) half_t g_Whh[SZ_WIH];
__device__ __align__(16) half_t g_Wpq[2 * NDIM * HDIM];   // [Wep; Weq[:, :1024]]
__device__ __align__(16) half_t g_Wq2[NDIM * EDIM];       // Weq[:, 1024:]
__device__ __align__(16) half_t g_Wpr[SZ_WPR];            // row-interleaved mean/std
__device__ __align__(16) half_t g_Wpo[SZ_WPR];

// ------------------------------- helpers ------------------------------------
__device__ __forceinline__ float sigmoidf_(float x) { return 1.0f / (1.0f + __expf(-x)); }
__device__ __forceinline__ float tanhf_(float x)    { return 1.0f - 2.0f / (__expf(2.0f * x) + 1.0f); }
__device__ __forceinline__ float softplusf_(float x) {
    return fmaxf(x, 0.0f) + log1pf(__expf(-fabsf(x)));
}
__device__ __forceinline__ uint32_t pack_h2(half_t a, half_t b) {
    __half2 t(a, b);
    return *reinterpret_cast<uint32_t*>(&t);
}
__device__ __forceinline__ void split_h(float v, half_t& h, half_t& l) {
    h = __float2half_rn(v);
    l = __float2half_rn(v - __half2float(h));
}
__device__ __forceinline__ void split_store4(float4 v, half_t* hdst, half_t* ldst, size_t idx4) {
    half_t h0, h1, h2, h3, l0, l1, l2, l3;
    split_h(v.x, h0, l0); split_h(v.y, h1, l1);
    split_h(v.z, h2, l2); split_h(v.w, h3, l3);
    reinterpret_cast<uint2*>(hdst)[idx4] = make_uint2(pack_h2(h0, h1), pack_h2(h2, h3));
    reinterpret_cast<uint2*>(ldst)[idx4] = make_uint2(pack_h2(l0, l1), pack_h2(l2, l3));
}
__device__ __forceinline__ uint2 conv4(float4 v) {
    return make_uint2(pack_h2(__float2half_rn(v.x), __float2half_rn(v.y)),
                      pack_h2(__float2half_rn(v.z), __float2half_rn(v.w)));
}
__device__ __forceinline__ void ldsm4(uint32_t* r, uint32_t addr) {
    asm volatile("ldmatrix.sync.aligned.m8n8.x4.shared.b16 {%0,%1,%2,%3}, [%4];"
                 : "=r"(r[0]), "=r"(r[1]), "=r"(r[2]), "=r"(r[3]) : "r"(addr));
}
__device__ __forceinline__ void mma_f16(float* c, const uint32_t* a, uint32_t b0, uint32_t b1) {
    asm volatile("mma.sync.aligned.m16n8k16.row.col.f32.f16.f16.f32 "
                 "{%0,%1,%2,%3}, {%4,%5,%6,%7}, {%8,%9}, {%0,%1,%2,%3};"
                 : "+f"(c[0]), "+f"(c[1]), "+f"(c[2]), "+f"(c[3])
                 : "r"(a[0]), "r"(a[1]), "r"(a[2]), "r"(a[3]), "r"(b0), "r"(b1));
}
__device__ __forceinline__ void cp16(uint32_t dst, const void* src) {
    asm volatile("cp.async.cg.shared.global [%0], [%1], 16;" :: "r"(dst), "l"(src));
}
__device__ __forceinline__ void cp_commit() {
    asm volatile("cp.async.commit_group;" ::: "memory");
}
__device__ __forceinline__ void cp_wait1() {
    asm volatile("cp.async.wait_group 1;" ::: "memory");
}

// -------------------- one-shot prep (all converts, flat dispatch) -----------
#define N_OBS  ((int)(LOBS / 4))          // 8388608
#define N_WIH  (SZ_WIH / 4)               // 786432
#define N_WSA  (SZ_WSA / 4)               // 40960
#define N_WEP  (SZ_WEP / 4)               // 262144
#define N_ILV  (SZ_WPR / 4)               // 65536
#define N_H0   ((int)(BH / 4))            // 131072
#define N_SP   ((int)(BS / 4))            // 16384
#define N_ACT  (LACT / 4)                 // 262144
#define N_TOT  (N_OBS + 2 * N_WIH + N_WSA + 3 * N_WEP + 2 * N_ILV + N_H0 + N_SP + N_ACT)

__global__ void prep_kernel(
    const float* __restrict__ Wih_f, const float* __restrict__ Whh_f,
    const float* __restrict__ Wsa_f, const float* __restrict__ Wep_f,
    const float* __restrict__ Weq_f, const float* __restrict__ Wpr_f,
    const float* __restrict__ Wpo_f,
    const float* __restrict__ prev_hidden, const float* __restrict__ prev_state,
    const float* __restrict__ nt0, const float* __restrict__ actions,
    const float* __restrict__ obs,
    half_t* __restrict__ Wih, half_t* __restrict__ Whh, half_t* __restrict__ Wsa,
    half_t* __restrict__ Wpq, half_t* __restrict__ Wq2,
    half_t* __restrict__ Wpr, half_t* __restrict__ Wpo,
    half_t* __restrict__ hh, half_t* __restrict__ hl,
    half_t* __restrict__ sph, half_t* __restrict__ spl,
    half_t* __restrict__ ah, half_t* __restrict__ al,
    half_t* __restrict__ oh, half_t* __restrict__ ol)
{
    int i = blockIdx.x * blockDim.x + threadIdx.x;
    if (i < N_OBS) {
        split_store4(reinterpret_cast<const float4*>(obs)[i], oh, ol, i);
        return;
    }
    i -= N_OBS;
    if (i < N_WIH) {
        reinterpret_cast<uint2*>(Wih)[i] = conv4(reinterpret_cast<const float4*>(Wih_f)[i]);
        return;
    }
    i -= N_WIH;
    if (i < N_WIH) {
        reinterpret_cast<uint2*>(Whh)[i] = conv4(reinterpret_cast<const float4*>(Whh_f)[i]);
        return;
    }
    i -= N_WIH;
    if (i < N_WSA) {
        reinterpret_cast<uint2*>(Wsa)[i] = conv4(reinterpret_cast<const float4*>(Wsa_f)[i]);
        return;
    }
    i -= N_WSA;
    if (i < N_WEP) {   // Wep -> Wpq rows [0,1024)
        reinterpret_cast<uint2*>(Wpq)[i] = conv4(reinterpret_cast<const float4*>(Wep_f)[i]);
        return;
    }
    i -= N_WEP;
    if (i < N_WEP) {   // Weq[:, :1024] -> Wpq rows [1024,2048)
        int n = i >> 8, k4 = i & 255;
        float4 v = *reinterpret_cast<const float4*>(Weq_f + (size_t)n * 2048 + k4 * 4);
        reinterpret_cast<uint2*>(Wpq)[N_WEP + i] = conv4(v);
        return;
    }
    i -= N_WEP;
    if (i < N_WEP) {   // Weq[:, 1024:] -> Wq2
        int n = i >> 8, k4 = i & 255;
        float4 v = *reinterpret_cast<const float4*>(Weq_f + (size_t)n * 2048 + 1024 + k4 * 4);
        reinterpret_cast<uint2*>(Wq2)[i] = conv4(v);
        return;
    }
    i -= N_WEP;
    if (i < N_ILV) {   // Wpr interleaved
        int r = i >> 8, k4 = i & 255;
        int sr = (r & 1) ? (r >> 1) + SDIM : (r >> 1);
        float4 v = *reinterpret_cast<const float4*>(Wpr_f + (size_t)sr * NDIM + k4 * 4);
        reinterpret_cast<uint2*>(Wpr)[i] = conv4(v);
        return;
    }
    i -= N_ILV;
    if (i < N_ILV) {   // Wpo interleaved
        int r = i >> 8, k4 = i & 255;
        int sr = (r & 1) ? (r >> 1) + SDIM : (r >> 1);
        float4 v = *reinterpret_cast<const float4*>(Wpo_f + (size_t)sr * NDIM + k4 * 4);
        reinterpret_cast<uint2*>(Wpo)[i] = conv4(v);
        return;
    }
    i -= N_ILV;
    if (i < N_H0) {
        split_store4(reinterpret_cast<const float4*>(prev_hidden)[i], hh, hl, i);
        return;
    }
    i -= N_H0;
    if (i < N_SP) {
        float4 v = reinterpret_cast<const float4*>(prev_state)[i];
        float s = nt0[i >> 5];
        v.x *= s; v.y *= s; v.z *= s; v.w *= s;
        split_store4(v, sph, spl, i);
        return;
    }
    i -= N_SP;
    if (i < N_ACT) {
        split_store4(reinterpret_cast<const float4*>(actions)[i], ah, al, i);
    }
}

// ------------------------------ GEMM args -----------------------------------
struct G {
    const half_t *Ah, *Al;     // k < kSplit, row stride sA
    const half_t *A2h, *A2l;   // k >= kSplit, row stride sA2
    const half_t* W;           // N x K fp16 row-major
    const float* bias;
    float* C; float* C2;       // EPI0: C out. EPI2: mean/std. EPI3: C = qe partial
    const float* noise;        // EPI2
    float* S;                  // EPI2
    half_t *Ch, *Cl;           // EPI1: out hi/lo. EPI3: pe out hi/lo
    half_t *Sh, *Sl;           // EPI2: spost*nt hi/lo. EPI3: qe out hi/lo
    const float* ntNext;       // EPI2
    int K, kSplit, sA, sA2;
};

// -------- fp16 2-pass tensor-core GEMM, cp.async 3-stage (C = A @ W^T) ------
// EPI: 0 bias->fp32; 1 bias+relu->fp16 hi/lo; 2 interleaved heads;
//      3 merged pe|qe (n<1024: bias+relu->Ch/Cl; else: +partial, relu->Sh/Sl)
template<int BM, int BN, int WM, int WN, int NWARPS, int EPI>
__global__ __launch_bounds__(NWARPS * 32, 1)
void gemm_tc(G g0, G g1, int N)
{
    constexpr int THREADS = NWARPS * 32;
    constexpr int BK  = 32;
    constexpr int LDS = BK + 8;
    constexpr int WTM = BM / WM;
    constexpr int WTN = BN / WN;
    constexpr int FM  = WTM / 16;
    constexpr int FN  = WTN / 8;
    static_assert(FN % 2 == 0, "");
    static_assert(WM * WN == NWARPS, "");
    constexpr int ACH = BM * 4;
    constexpr int BCH = BN * 4;
    constexpr int CH_TOT = 2 * ACH + BCH;
    constexpr int ABLK_B = BM * LDS * 2;
    constexpr int BBLK_B = BN * LDS * 2;
    constexpr int STG_B  = 2 * ABLK_B + BBLK_B;

    extern __shared__ __align__(16) char dynsmem[];
    const uint32_t sbase = (uint32_t)__cvta_generic_to_shared(dynsmem);

    const G g = (blockIdx.z == 0) ? g0 : g1;
    const int K = g.K;
    const int tid  = threadIdx.x;
    const int wid  = tid >> 5;
    const int lane = tid & 31;
    const int wm = wid % WM, wn = wid / WM;
    const int bm = blockIdx.y * BM, bn = blockIdx.x * BN;

    float acc[FM][FN][4];
#pragma unroll
    for (int i = 0; i < FM; i++)
#pragma unroll
        for (int j = 0; j < FN; j++)
#pragma unroll
            for (int q = 0; q < 4; q++) acc[i][j][q] = 0.0f;

    auto loadStage = [&](int ck, int buf) {
        const int ko = ck * BK;
        const half_t *ah, *al; int kb, sa;
        if (ko < g.kSplit) { ah = g.Ah;  al = g.Al;  kb = ko;             sa = g.sA;  }
        else               { ah = g.A2h; al = g.A2l; kb = ko - g.kSplit;  sa = g.sA2; }
        const uint32_t sb = sbase + (uint32_t)buf * STG_B;
#pragma unroll 2
        for (int i = tid; i < CH_TOT; i += THREADS) {
            const half_t* src; uint32_t dst;
            if (i < ACH) {
                int r = i >> 2, c = i & 3;
                src = ah + (size_t)(bm + r) * sa + kb + c * 8;
                dst = sb + (uint32_t)(r * LDS + c * 8) * 2;
            } else if (i < 2 * ACH) {
                int j = i - ACH;
                int r = j >> 2, c = j & 3;
                src = al + (size_t)(bm + r) * sa + kb + c * 8;
                dst = sb + ABLK_B + (uint32_t)(r * LDS + c * 8) * 2;
            } else {
                int j = i - 2 * ACH;
                int r = j >> 2, c = j & 3;
                src = g.W + (size_t)(bn + r) * K + ko + c * 8;
                dst = sb + 2 * ABLK_B + (uint32_t)(r * LDS + c * 8) * 2;
            }
            cp16(dst, src);
        }
    };

    const int kT = K / BK;
    loadStage(0, 0); cp_commit();
    loadStage(1, 1); cp_commit();

    int cbuf = 0, lbuf = 2;
    for (int kt = 0; kt < kT; kt++) {
        cp_wait1();
        __syncthreads();
        if (kt + 2 < kT) loadStage(kt + 2, lbuf);
        cp_commit();

        const uint32_t aBaseH = sbase + (uint32_t)cbuf * STG_B;
        const uint32_t aBaseL = aBaseH + ABLK_B;
        const uint32_t bBase  = aBaseH + 2 * ABLK_B;

#pragma unroll
        for (int k16 = 0; k16 < 2; k16++) {
            uint32_t afh[FM][4], afl[FM][4];
            const int acol = k16 * 16 + ((lane >> 4) << 3);
#pragma unroll
            for (int fm = 0; fm < FM; fm++) {
                const int arow = wm * WTM + fm * 16 + (lane & 15);
                const uint32_t aoff = (uint32_t)(arow * LDS + acol) * 2u;
                ldsm4(afh[fm], aBaseH + aoff);
                ldsm4(afl[fm], aBaseL + aoff);
            }
            const int brlane = ((lane >> 4) << 3) + (lane & 7);
            const int bcol   = k16 * 16 + (((lane >> 3) & 1) << 3);
#pragma unroll
            for (int fn2 = 0; fn2 < FN / 2; fn2++) {
                const int brow = wn * WTN + fn2 * 16 + brlane;
                const uint32_t boff = (uint32_t)(brow * LDS + bcol) * 2u;
                uint32_t bh[4];
                ldsm4(bh, bBase + boff);
#pragma unroll
                for (int fm = 0; fm < FM; fm++) {
                    float* c0 = acc[fm][2 * fn2];
                    float* c1 = acc[fm][2 * fn2 + 1];
                    mma_f16(c0, afh[fm], bh[0], bh[1]);
                    mma_f16(c0, afl[fm], bh[0], bh[1]);
                    mma_f16(c1, afh[fm], bh[2], bh[3]);
                    mma_f16(c1, afl[fm], bh[2], bh[3]);
                }
            }
        }
        __syncthreads();
        cbuf = (cbuf == 2) ? 0 : cbuf + 1;
        lbuf = (lbuf == 2) ? 0 : lbuf + 1;
    }

    const int gid = lane >> 2, tig = lane & 3;
#pragma unroll
    for (int fm = 0; fm < FM; fm++) {
        const int m0 = bm + wm * WTM + fm * 16 + gid;
#pragma unroll
        for (int fn = 0; fn < FN; fn++) {
            const int n0 = bn + wn * WTN + fn * 8 + tig * 2;
            if (EPI == 2) {
                const int i = n0 >> 1;
                const float bm_ = g.bias[i], bs_ = g.bias[i + SDIM];
                float me0 = acc[fm][fn][0] + bm_;
                float sd0 = softplusf_(acc[fm][fn][1] + bs_) + 0.1f;
                float me1 = acc[fm][fn][2] + bm_;
                float sd1 = softplusf_(acc[fm][fn][3] + bs_) + 0.1f;
                const size_t o0 = (size_t)m0 * SDIM + i;
                const size_t o1 = (size_t)(m0 + 8) * SDIM + i;
                g.C [o0] = me0;  g.C [o1] = me1;
                g.C2[o0] = sd0;  g.C2[o1] = sd1;
                float s0 = fmaf(sd0, g.noise[o0], me0);
                float s1 = fmaf(sd1, g.noise[o1], me1);
                g.S[o0] = s0;  g.S[o1] = s1;
                if (g.Sh) {
                    float sc0 = s0 * g.ntNext[m0];
                    float sc1 = s1 * g.ntNext[m0 + 8];
                    half_t h, l;
                    split_h(sc0, h, l); g.Sh[o0] = h; g.Sl[o0] = l;
                    split_h(sc1, h, l); g.Sh[o1] = h; g.Sl[o1] = l;
                }
            } else if (EPI == 3) {
                // merged pe|qe, virtual N=2048
                if (n0 < NDIM) {
                    const float b0 = g.bias[n0], b1 = g.bias[n0 + 1];
                    float v00 = fmaxf(acc[fm][fn][0] + b0, 0.0f);
                    float v01 = fmaxf(acc[fm][fn][1] + b1, 0.0f);
                    float v10 = fmaxf(acc[fm][fn][2] + b0, 0.0f);
                    float v11 = fmaxf(acc[fm][fn][3] + b1, 0.0f);
                    half_t h0, l0, h1, l1;
                    split_h(v00, h0, l0); split_h(v01, h1, l1);
                    *reinterpret_cast<uint32_t*>(g.Ch + (size_t)m0 * NDIM + n0) = pack_h2(h0, h1);
                    *reinterpret_cast<uint32_t*>(g.Cl + (size_t)m0 * NDIM + n0) = pack_h2(l0, l1);
                    split_h(v10, h0, l0); split_h(v11, h1, l1);
                    *reinterpret_cast<uint32_t*>(g.Ch + (size_t)(m0 + 8) * NDIM + n0) = pack_h2(h0, h1);
                    *reinterpret_cast<uint32_t*>(g.Cl + (size_t)(m0 + 8) * NDIM + n0) = pack_h2(l0, l1);
                } else {
                    const int nq = n0 - NDIM;
                    float2 p0 = *reinterpret_cast<const float2*>(g.C + (size_t)m0 * NDIM + nq);
                    float2 p1 = *reinterpret_cast<const float2*>(g.C + (size_t)(m0 + 8) * NDIM + nq);
                    float v00 = fmaxf(acc[fm][fn][0] + p0.x, 0.0f);
                    float v01 = fmaxf(acc[fm][fn][1] + p0.y, 0.0f);
                    float v10 = fmaxf(acc[fm][fn][2] + p1.x, 0.0f);
                    float v11 = fmaxf(acc[fm][fn][3] + p1.y, 0.0f);
                    half_t h0, l0, h1, l1;
                    split_h(v00, h0, l0); split_h(v01, h1, l1);
                    *reinterpret_cast<uint32_t*>(g.Sh + (size_t)m0 * NDIM + nq) = pack_h2(h0, h1);
                    *reinterpret_cast<uint32_t*>(g.Sl + (size_t)m0 * NDIM + nq) = pack_h2(l0, l1);
                    split_h(v10, h0, l0); split_h(v11, h1, l1);
                    *reinterpret_cast<uint32_t*>(g.Sh + (size_t)(m0 + 8) * NDIM + nq) = pack_h2(h0, h1);
                    *reinterpret_cast<uint32_t*>(g.Sl + (size_t)(m0 + 8) * NDIM + nq) = pack_h2(l0, l1);
                }
            } else {
                const float b0 = g.bias[n0], b1 = g.bias[n0 + 1];
                float v00 = acc[fm][fn][0] + b0, v01 = acc[fm][fn][1] + b1;
                float v10 = acc[fm][fn][2] + b0, v11 = acc[fm][fn][3] + b1;
                if (EPI == 1) {
                    v00 = fmaxf(v00, 0.0f); v01 = fmaxf(v01, 0.0f);
                    v10 = fmaxf(v10, 0.0f); v11 = fmaxf(v11, 0.0f);
                    half_t h0, l0, h1, l1;
                    split_h(v00, h0, l0); split_h(v01, h1, l1);
                    *reinterpret_cast<uint32_t*>(g.Ch + (size_t)m0 * N + n0) = pack_h2(h0, h1);
                    *reinterpret_cast<uint32_t*>(g.Cl + (size_t)m0 * N + n0) = pack_h2(l0, l1);
                    split_h(v10, h0, l0); split_h(v11, h1, l1);
                    *reinterpret_cast<uint32_t*>(g.Ch + (size_t)(m0 + 8) * N + n0) = pack_h2(h0, h1);
                    *reinterpret_cast<uint32_t*>(g.Cl + (size_t)(m0 + 8) * N + n0) = pack_h2(l0, l1);
                } else {
                    *reinterpret_cast<float2*>(g.C + (size_t)m0 * N + n0)       = make_float2(v00, v01);
                    *reinterpret_cast<float2*>(g.C + (size_t)(m0 + 8) * N + n0) = make_float2(v10, v11);
                }
            }
        }
    }
}

// ---------------- GRU gates + h split ----------------------------------------
__global__ void gru_gate_kernel(const float* __restrict__ hprev, float* __restrict__ hnew,
                                half_t* __restrict__ hh, half_t* __restrict__ hl)
{
    const int H4 = HDIM / 4;
    int idx = blockIdx.x * blockDim.x + threadIdx.x;
    if (idx >= BDIM * H4) return;
    int m = idx / H4, j4 = idx % H4;
    const float4* gi = reinterpret_cast<const float4*>(g_gi + (size_t)m * 3 * HDIM);
    const float4* gh = reinterpret_cast<const float4*>(g_gh + (size_t)m * 3 * HDIM);
    float4 ir = gi[j4], iz = gi[j4 + H4], in_ = gi[j4 + 2 * H4];
    float4 hr = gh[j4], hz = gh[j4 + H4], hn = gh[j4 + 2 * H4];
    float4 hp = reinterpret_cast<const float4*>(hprev + (size_t)m * HDIM)[j4];
    float4 o;
    { float r = sigmoidf_(ir.x + hr.x), z = sigmoidf_(iz.x + hz.x);
      float n = tanhf_(in_.x + r * hn.x); o.x = (1.0f - z) * n + z * hp.x; }
    { float r = sigmoidf_(ir.y + hr.y), z = sigmoidf_(iz.y + hz.y);
      float n = tanhf_(in_.y + r * hn.y); o.y = (1.0f - z) * n + z * hp.y; }
    { float r = sigmoidf_(ir.z + hr.z), z = sigmoidf_(iz.z + hz.z);
      float n = tanhf_(in_.z + r * hn.z); o.z = (1.0f - z) * n + z * hp.z; }
    { float r = sigmoidf_(ir.w + hr.w), z = sigmoidf_(iz.w + hz.w);
      float n = tanhf_(in_.w + r * hn.w); o.w = (1.0f - z) * n + z * hp.w; }
    reinterpret_cast<float4*>(hnew)[idx] = o;
    split_store4(o, hh, hl, idx);
}

// ------------------------------- launch --------------------------------------
extern "C" void kernel_launch(void* const* d_in, const int* in_sizes, int n_in,
                              void* d_out, int out_size)
{
    (void)in_sizes; (void)n_in; (void)out_size;
    const float* prev_hidden = (const float*)d_in[0];
    const float* prev_state  = (const float*)d_in[1];
    const float* actions     = (const float*)d_in[2];
    const float* obs         = (const float*)d_in[3];
    const float* non_terms   = (const float*)d_in[4];
    const float* prior_noise = (const float*)d_in[5];
    const float* post_noise  = (const float*)d_in[6];
    const float* W_sa = (const float*)d_in[7];
    const float* b_sa = (const float*)d_in[8];
    const float* W_ih = (const float*)d_in[9];
    const float* W_hh = (const float*)d_in[10];
    const float* b_ih = (const float*)d_in[11];
    const float* b_hh = (const float*)d_in[12];
    const float* W_ep = (const float*)d_in[13];
    const float* b_ep = (const float*)d_in[14];
    const float* W_pr = (const float*)d_in[15];
    const float* b_pr = (const float*)d_in[16];
    const float* W_eq = (const float*)d_in[17];
    const float* b_eq = (const float*)d_in[18];
    const float* W_po = (const float*)d_in[19];
    const float* b_po = (const float*)d_in[20];

    float* out = (float*)d_out;
    const size_t off_pm     = LBH;
    const size_t off_ps     = LBH + 1 * LBS;
    const size_t off_sprior = LBH + 2 * LBS;
    const size_t off_qm     = LBH + 3 * LBS;
    const size_t off_qs     = LBH + 4 * LBS;
    const size_t off_spost  = LBH + 5 * LBS;

    float *gi, *gh, *qp;
    cudaGetSymbolAddress((void**)&gi, g_gi);
    cudaGetSymbolAddress((void**)&gh, g_gh);
    cudaGetSymbolAddress((void**)&qp, g_qp);
    half_t *x_h, *x_l, *h_h, *h_l, *pe_h, *pe_l, *qe_h, *qe_l, *ob_h, *ob_l;
    half_t *sp_h, *sp_l, *act_h, *act_l;
    cudaGetSymbolAddress((void**)&x_h,  g_x_h);  cudaGetSymbolAddress((void**)&x_l,  g_x_l);
    cudaGetSymbolAddress((void**)&h_h,  g_h_h);  cudaGetSymbolAddress((void**)&h_l,  g_h_l);
    cudaGetSymbolAddress((void**)&pe_h, g_pe_h); cudaGetSymbolAddress((void**)&pe_l, g_pe_l);
    cudaGetSymbolAddress((void**)&qe_h, g_qe_h); cudaGetSymbolAddress((void**)&qe_l, g_qe_l);
    cudaGetSymbolAddress((void**)&ob_h, g_ob_h); cudaGetSymbolAddress((void**)&ob_l, g_ob_l);
    cudaGetSymbolAddress((void**)&sp_h, g_sp_h); cudaGetSymbolAddress((void**)&sp_l, g_sp_l);
    cudaGetSymbolAddress((void**)&act_h, g_act_h); cudaGetSymbolAddress((void**)&act_l, g_act_l);

    half_t *Wsa, *Wih, *Whh, *Wpq, *Wq2, *Wpr, *Wpo;
    cudaGetSymbolAddress((void**)&Wsa, g_Wsa);
    cudaGetSymbolAddress((void**)&Wih, g_Wih);
    cudaGetSymbolAddress((void**)&Whh, g_Whh);
    cudaGetSymbolAddress((void**)&Wpq, g_Wpq);
    cudaGetSymbolAddress((void**)&Wq2, g_Wq2);
    cudaGetSymbolAddress((void**)&Wpr, g_Wpr);
    cudaGetSymbolAddress((void**)&Wpo, g_Wpo);

    // ---- dynamic smem ----
    const int SM_BIG  = 3 * (2 * 128 * 40 + 192 * 40) * 2;   // 107520
    const int SM_PQ   = 3 * (2 * 64 * 40 + 128 * 40) * 2;    // 61440
    const int SM_X    = 3 * (2 * 64 * 40 + 64 * 40) * 2;     // 46080
    const int SM_HEAD = 3 * (2 * 32 * 40 + 64 * 40) * 2;     // 30720
    cudaFuncSetAttribute((const void*)gemm_tc<128, 192, 4, 3, 12, 0>,
                         cudaFuncAttributeMaxDynamicSharedMemorySize, SM_BIG);
    cudaFuncSetAttribute((const void*)gemm_tc<64, 128, 2, 4, 8, 0>,
                         cudaFuncAttributeMaxDynamicSharedMemorySize, SM_PQ);
    cudaFuncSetAttribute((const void*)gemm_tc<64, 128, 2, 4, 8, 3>,
                         cudaFuncAttributeMaxDynamicSharedMemorySize, SM_PQ);
    cudaFuncSetAttribute((const void*)gemm_tc<64, 64, 2, 4, 8, 1>,
                         cudaFuncAttributeMaxDynamicSharedMemorySize, SM_X);
    cudaFuncSetAttribute((const void*)gemm_tc<32, 64, 1, 4, 4, 2>,
                         cudaFuncAttributeMaxDynamicSharedMemorySize, SM_HEAD);

    // ---- launch 0: one-shot prep (all conversions) ----
    prep_kernel<<<N_TOT / 256, 256>>>(
        W_ih, W_hh, W_sa, W_ep, W_eq, W_pr, W_po,
        prev_hidden, prev_state, non_terms, actions, obs,
        Wih, Whh, Wsa, Wpq, Wq2, Wpr, Wpo,
        h_h, h_l, sp_h, sp_l, act_h, act_l, ob_h, ob_l);

    // ---- launch 1: batched qe obs-partial  qp = obs @ Wq2^T + b_eq ----
    {
        G a{ob_h, ob_l, ob_h, ob_l, Wq2, b_eq, qp, nullptr, nullptr, nullptr,
            nullptr, nullptr, nullptr, nullptr, nullptr, EDIM, EDIM, EDIM, EDIM};
        gemm_tc<64, 128, 2, 4, 8, 0><<<dim3(NDIM / 128, LSTEPS * BDIM / 64, 1), 256, SM_PQ>>>(
            a, a, NDIM);
    }

    const int KSA = SDIM + ADIM;

    for (int t = 0; t < LSTEPS; t++) {
        const float* hprev = (t == 0) ? prev_hidden : out + (size_t)(t - 1) * BH;
        float* hnew = out + (size_t)t * BH;
        const half_t* act_ht = act_h + (size_t)t * BDIM * ADIM;
        const half_t* act_lt = act_l + (size_t)t * BDIM * ADIM;
        const float* ntNext = non_terms + (size_t)((t + 1 < LSTEPS) ? t + 1 : t) * BDIM;
        float* qp_t = qp + (size_t)t * BDIM * NDIM;

        // x = relu([spost*nt, a] @ Wsa^T + b_sa) -> fp16 hi/lo   (idx 2 at t=0)
        {
            G a{sp_h, sp_l, act_ht, act_lt, Wsa, b_sa,
                nullptr, nullptr, nullptr, nullptr, x_h, x_l,
                nullptr, nullptr, nullptr, KSA, SDIM, SDIM, ADIM};
            gemm_tc<64, 64, 2, 4, 8, 1><<<dim3(HDIM / 64, BDIM / 64, 1), 256, SM_X>>>(
                a, a, HDIM);
        }
        // gi = x @ Wih^T + b_ih ; gh = h @ Whh^T + b_hh   (idx 3 at t=0 -> profiled)
        {
            G a0{x_h, x_l, x_h, x_l, Wih, b_ih, gi, nullptr, nullptr, nullptr,
                 nullptr, nullptr, nullptr, nullptr, nullptr, HDIM, HDIM, HDIM, HDIM};
            G a1{h_h, h_l, h_h, h_l, Whh, b_hh, gh, nullptr, nullptr, nullptr,
                 nullptr, nullptr, nullptr, nullptr, nullptr, HDIM, HDIM, HDIM, HDIM};
            gemm_tc<128, 192, 4, 3, 12, 0><<<dim3(3 * HDIM / 192, BDIM / 128, 2), 384, SM_BIG>>>(
                a0, a1, 3 * HDIM);
        }
        // GRU gates -> hnew fp32 + h hi/lo
        gru_gate_kernel<<<(int)(BH / 4 / 256), 256>>>(hprev, hnew, h_h, h_l);

        // merged pe|qe: N=2048, K=1024, A = h hi/lo
        {
            G a{h_h, h_l, h_h, h_l, Wpq, b_ep, qp_t, nullptr, nullptr, nullptr,
                pe_h, pe_l, qe_h, qe_l, nullptr, HDIM, HDIM, HDIM, HDIM};
            gemm_tc<64, 128, 2, 4, 8, 3><<<dim3(2 * NDIM / 128, BDIM / 64, 1), 256, SM_PQ>>>(
                a, a, 2 * NDIM);
        }
        // heads + reparameterized states (fused); posterior writes sp*ntNext hi/lo
        float* pm_o = out + off_pm + (size_t)t * BS;
        float* ps_o = out + off_ps + (size_t)t * BS;
        float* qm_o = out + off_qm + (size_t)t * BS;
        float* qs_o = out + off_qs + (size_t)t * BS;
        {
            G a0{pe_h, pe_l, pe_h, pe_l, Wpr, b_pr, pm_o, ps_o,
                 prior_noise + (size_t)t * BS, out + off_sprior + (size_t)t * BS,
                 nullptr, nullptr, nullptr, nullptr, nullptr, NDIM, NDIM, NDIM, NDIM};
            G a1{qe_h, qe_l, qe_h, qe_l, Wpo, b_po, qm_o, qs_o,
                 post_noise + (size_t)t * BS, out + off_spost + (size_t)t * BS,
                 nullptr, nullptr, sp_h, sp_l, ntNext, NDIM, NDIM, NDIM, NDIM};
            gemm_tc<32, 64, 1, 4, 4, 2><<<dim3(2 * SDIM / 64, BDIM / 32, 2), 128, SM_HEAD>>>(
                a0, a1, 2 * SDIM);
        }
    }
}

// round 10
// speedup vs baseline: 1.2754x; 1.0356x over previous
#include <cuda_runtime.h>
#include <cuda_fp16.h>
#include <math.h>
#include <stdint.h>

#define LSTEPS 64
#define BDIM   512
#define HDIM   1024
#define SDIM   128
#define ADIM   32
#define NDIM   1024
#define EDIM   1024

#define BH ((size_t)BDIM * HDIM)
#define BS ((size_t)BDIM * SDIM)
#define LBH ((size_t)LSTEPS * BH)
#define LBS ((size_t)LSTEPS * BS)
#define LACT (LSTEPS * BDIM * ADIM)
#define LOBS ((size_t)LSTEPS * BDIM * EDIM)

typedef __half half_t;

// ---------------- scratch: fp32 ---------------------------------------------
__device__ __align__(16) float g_gi[BDIM * 3 * HDIM];
__device__ __align__(16) float g_gh[BDIM * 3 * HDIM];
__device__ __align__(16) float g_qp[LOBS];            // qe obs-partial (+b_eq)

// ---------------- scratch: fp16 hi/lo activations ---------------------------
__device__ __align__(16) half_t g_x_h [BDIM * HDIM], g_x_l [BDIM * HDIM];
__device__ __align__(16) half_t g_h_h [BDIM * HDIM], g_h_l [BDIM * HDIM];
__device__ __align__(16) half_t g_pe_h[BDIM * NDIM], g_pe_l[BDIM * NDIM];
__device__ __align__(16) half_t g_qe_h[BDIM * NDIM], g_qe_l[BDIM * NDIM];
__device__ __align__(16) half_t g_sp_h[BDIM * SDIM], g_sp_l[BDIM * SDIM];
__device__ __align__(16) half_t g_act_h[LACT], g_act_l[LACT];
__device__ __align__(16) half_t g_ob_h[LOBS], g_ob_l[LOBS];

// ---------------- scratch: converted weights (fp16) -------------------------
#define SZ_WSA (HDIM * (SDIM + ADIM))
#define SZ_WIH (3 * HDIM * HDIM)
#define SZ_WEP (NDIM * HDIM)
#define SZ_WPR (2 * SDIM * NDIM)

__device__ __align__(16) half_t g_Wsa[SZ_WSA];
__device__ __align__(16) half_t g_Wih[SZ_WIH];
__device__ __align__(16) half_t g_Whh[SZ_WIH];
__device__ __align__(16) half_t g_Wpq[2 * NDIM * HDIM];   // [Wep; Weq[:, :1024]]
__device__ __align__(16) half_t g_Wq2[NDIM * EDIM];       // Weq[:, 1024:]
__device__ __align__(16) half_t g_Wpr[SZ_WPR];            // row-interleaved mean/std
__device__ __align__(16) half_t g_Wpo[SZ_WPR];

// ------------------------------- helpers ------------------------------------
__device__ __forceinline__ float sigmoidf_(float x) { return 1.0f / (1.0f + __expf(-x)); }
__device__ __forceinline__ float tanhf_(float x)    { return 1.0f - 2.0f / (__expf(2.0f * x) + 1.0f); }
__device__ __forceinline__ float softplusf_(float x) {
    return fmaxf(x, 0.0f) + log1pf(__expf(-fabsf(x)));
}
__device__ __forceinline__ uint32_t pack_h2(half_t a, half_t b) {
    __half2 t(a, b);
    return *reinterpret_cast<uint32_t*>(&t);
}
__device__ __forceinline__ void split_h(float v, half_t& h, half_t& l) {
    h = __float2half_rn(v);
    l = __float2half_rn(v - __half2float(h));
}
__device__ __forceinline__ void split_store4(float4 v, half_t* hdst, half_t* ldst, size_t idx4) {
    half_t h0, h1, h2, h3, l0, l1, l2, l3;
    split_h(v.x, h0, l0); split_h(v.y, h1, l1);
    split_h(v.z, h2, l2); split_h(v.w, h3, l3);
    reinterpret_cast<uint2*>(hdst)[idx4] = make_uint2(pack_h2(h0, h1), pack_h2(h2, h3));
    reinterpret_cast<uint2*>(ldst)[idx4] = make_uint2(pack_h2(l0, l1), pack_h2(l2, l3));
}
__device__ __forceinline__ uint2 conv4(float4 v) {
    return make_uint2(pack_h2(__float2half_rn(v.x), __float2half_rn(v.y)),
                      pack_h2(__float2half_rn(v.z), __float2half_rn(v.w)));
}
__device__ __forceinline__ void ldsm4(uint32_t* r, uint32_t addr) {
    asm volatile("ldmatrix.sync.aligned.m8n8.x4.shared.b16 {%0,%1,%2,%3}, [%4];"
                 : "=r"(r[0]), "=r"(r[1]), "=r"(r[2]), "=r"(r[3]) : "r"(addr));
}
__device__ __forceinline__ void mma_f16(float* c, const uint32_t* a, uint32_t b0, uint32_t b1) {
    asm volatile("mma.sync.aligned.m16n8k16.row.col.f32.f16.f16.f32 "
                 "{%0,%1,%2,%3}, {%4,%5,%6,%7}, {%8,%9}, {%0,%1,%2,%3};"
                 : "+f"(c[0]), "+f"(c[1]), "+f"(c[2]), "+f"(c[3])
                 : "r"(a[0]), "r"(a[1]), "r"(a[2]), "r"(a[3]), "r"(b0), "r"(b1));
}
__device__ __forceinline__ void cp16(uint32_t dst, const void* src) {
    asm volatile("cp.async.cg.shared.global [%0], [%1], 16;" :: "r"(dst), "l"(src));
}
__device__ __forceinline__ void cp_commit() {
    asm volatile("cp.async.commit_group;" ::: "memory");
}
__device__ __forceinline__ void cp_wait1() {
    asm volatile("cp.async.wait_group 1;" ::: "memory");
}

// -------------------- one-shot prep (all converts, flat dispatch) -----------
#define N_OBS  ((int)(LOBS / 4))
#define N_WIH  (SZ_WIH / 4)
#define N_WSA  (SZ_WSA / 4)
#define N_WEP  (SZ_WEP / 4)
#define N_ILV  (SZ_WPR / 4)
#define N_H0   ((int)(BH / 4))
#define N_SP   ((int)(BS / 4))
#define N_ACT  (LACT / 4)
#define N_TOT  (N_OBS + 2 * N_WIH + N_WSA + 3 * N_WEP + 2 * N_ILV + N_H0 + N_SP + N_ACT)

__global__ void prep_kernel(
    const float* __restrict__ Wih_f, const float* __restrict__ Whh_f,
    const float* __restrict__ Wsa_f, const float* __restrict__ Wep_f,
    const float* __restrict__ Weq_f, const float* __restrict__ Wpr_f,
    const float* __restrict__ Wpo_f,
    const float* __restrict__ prev_hidden, const float* __restrict__ prev_state,
    const float* __restrict__ nt0, const float* __restrict__ actions,
    const float* __restrict__ obs,
    half_t* __restrict__ Wih, half_t* __restrict__ Whh, half_t* __restrict__ Wsa,
    half_t* __restrict__ Wpq, half_t* __restrict__ Wq2,
    half_t* __restrict__ Wpr, half_t* __restrict__ Wpo,
    half_t* __restrict__ hh, half_t* __restrict__ hl,
    half_t* __restrict__ sph, half_t* __restrict__ spl,
    half_t* __restrict__ ah, half_t* __restrict__ al,
    half_t* __restrict__ oh, half_t* __restrict__ ol)
{
    int i = blockIdx.x * blockDim.x + threadIdx.x;
    if (i < N_OBS) {
        split_store4(reinterpret_cast<const float4*>(obs)[i], oh, ol, i);
        return;
    }
    i -= N_OBS;
    if (i < N_WIH) {
        reinterpret_cast<uint2*>(Wih)[i] = conv4(reinterpret_cast<const float4*>(Wih_f)[i]);
        return;
    }
    i -= N_WIH;
    if (i < N_WIH) {
        reinterpret_cast<uint2*>(Whh)[i] = conv4(reinterpret_cast<const float4*>(Whh_f)[i]);
        return;
    }
    i -= N_WIH;
    if (i < N_WSA) {
        reinterpret_cast<uint2*>(Wsa)[i] = conv4(reinterpret_cast<const float4*>(Wsa_f)[i]);
        return;
    }
    i -= N_WSA;
    if (i < N_WEP) {
        reinterpret_cast<uint2*>(Wpq)[i] = conv4(reinterpret_cast<const float4*>(Wep_f)[i]);
        return;
    }
    i -= N_WEP;
    if (i < N_WEP) {
        int n = i >> 8, k4 = i & 255;
        float4 v = *reinterpret_cast<const float4*>(Weq_f + (size_t)n * 2048 + k4 * 4);
        reinterpret_cast<uint2*>(Wpq)[N_WEP + i] = conv4(v);
        return;
    }
    i -= N_WEP;
    if (i < N_WEP) {
        int n = i >> 8, k4 = i & 255;
        float4 v = *reinterpret_cast<const float4*>(Weq_f + (size_t)n * 2048 + 1024 + k4 * 4);
        reinterpret_cast<uint2*>(Wq2)[i] = conv4(v);
        return;
    }
    i -= N_WEP;
    if (i < N_ILV) {
        int r = i >> 8, k4 = i & 255;
        int sr = (r & 1) ? (r >> 1) + SDIM : (r >> 1);
        float4 v = *reinterpret_cast<const float4*>(Wpr_f + (size_t)sr * NDIM + k4 * 4);
        reinterpret_cast<uint2*>(Wpr)[i] = conv4(v);
        return;
    }
    i -= N_ILV;
    if (i < N_ILV) {
        int r = i >> 8, k4 = i & 255;
        int sr = (r & 1) ? (r >> 1) + SDIM : (r >> 1);
        float4 v = *reinterpret_cast<const float4*>(Wpo_f + (size_t)sr * NDIM + k4 * 4);
        reinterpret_cast<uint2*>(Wpo)[i] = conv4(v);
        return;
    }
    i -= N_ILV;
    if (i < N_H0) {
        split_store4(reinterpret_cast<const float4*>(prev_hidden)[i], hh, hl, i);
        return;
    }
    i -= N_H0;
    if (i < N_SP) {
        float4 v = reinterpret_cast<const float4*>(prev_state)[i];
        float s = nt0[i >> 5];
        v.x *= s; v.y *= s; v.z *= s; v.w *= s;
        split_store4(v, sph, spl, i);
        return;
    }
    i -= N_SP;
    if (i < N_ACT) {
        split_store4(reinterpret_cast<const float4*>(actions)[i], ah, al, i);
    }
}

// ------------------------------ GEMM args -----------------------------------
struct G {
    const half_t *Ah, *Al;
    const half_t *A2h, *A2l;
    const half_t* W;
    const float* bias;
    float* C; float* C2;
    const float* noise;
    float* S;
    half_t *Ch, *Cl;
    half_t *Sh, *Sl;
    const float* ntNext;
    int K, kSplit, sA, sA2;
};

// -------- fp16 2-pass tensor-core GEMM, cp.async 3-stage (C = A @ W^T) ------
// EPI: 0 bias->fp32; 1 bias+relu->fp16 hi/lo; 2 interleaved heads;
//      3 merged pe|qe (n<1024: bias+relu->Ch/Cl; else: +partial, relu->Sh/Sl)
template<int BM, int BN, int WM, int WN, int NWARPS, int EPI, int MINB>
__global__ __launch_bounds__(NWARPS * 32, MINB)
void gemm_tc(G g0, G g1, int N)
{
    constexpr int THREADS = NWARPS * 32;
    constexpr int BK  = 32;
    constexpr int LDS = BK + 8;
    constexpr int WTM = BM / WM;
    constexpr int WTN = BN / WN;
    constexpr int FM  = WTM / 16;
    constexpr int FN  = WTN / 8;
    static_assert(FN % 2 == 0, "");
    static_assert(WM * WN == NWARPS, "");
    constexpr int ACH = BM * 4;
    constexpr int BCH = BN * 4;
    constexpr int CH_TOT = 2 * ACH + BCH;
    constexpr int ABLK_B = BM * LDS * 2;
    constexpr int BBLK_B = BN * LDS * 2;
    constexpr int STG_B  = 2 * ABLK_B + BBLK_B;

    extern __shared__ __align__(16) char dynsmem[];
    const uint32_t sbase = (uint32_t)__cvta_generic_to_shared(dynsmem);

    const G g = (blockIdx.z == 0) ? g0 : g1;
    const int K = g.K;
    const int tid  = threadIdx.x;
    const int wid  = tid >> 5;
    const int lane = tid & 31;
    const int wm = wid % WM, wn = wid / WM;
    const int bm = blockIdx.y * BM, bn = blockIdx.x * BN;

    float acc[FM][FN][4];
#pragma unroll
    for (int i = 0; i < FM; i++)
#pragma unroll
        for (int j = 0; j < FN; j++)
#pragma unroll
            for (int q = 0; q < 4; q++) acc[i][j][q] = 0.0f;

    auto loadStage = [&](int ck, int buf) {
        const int ko = ck * BK;
        const half_t *ah, *al; int kb, sa;
        if (ko < g.kSplit) { ah = g.Ah;  al = g.Al;  kb = ko;             sa = g.sA;  }
        else               { ah = g.A2h; al = g.A2l; kb = ko - g.kSplit;  sa = g.sA2; }
        const uint32_t sb = sbase + (uint32_t)buf * STG_B;
#pragma unroll 2
        for (int i = tid; i < CH_TOT; i += THREADS) {
            const half_t* src; uint32_t dst;
            if (i < ACH) {
                int r = i >> 2, c = i & 3;
                src = ah + (size_t)(bm + r) * sa + kb + c * 8;
                dst = sb + (uint32_t)(r * LDS + c * 8) * 2;
            } else if (i < 2 * ACH) {
                int j = i - ACH;
                int r = j >> 2, c = j & 3;
                src = al + (size_t)(bm + r) * sa + kb + c * 8;
                dst = sb + ABLK_B + (uint32_t)(r * LDS + c * 8) * 2;
            } else {
                int j = i - 2 * ACH;
                int r = j >> 2, c = j & 3;
                src = g.W + (size_t)(bn + r) * K + ko + c * 8;
                dst = sb + 2 * ABLK_B + (uint32_t)(r * LDS + c * 8) * 2;
            }
            cp16(dst, src);
        }
    };

    const int kT = K / BK;
    loadStage(0, 0); cp_commit();
    loadStage(1, 1); cp_commit();

    int cbuf = 0, lbuf = 2;
    for (int kt = 0; kt < kT; kt++) {
        cp_wait1();
        __syncthreads();
        if (kt + 2 < kT) loadStage(kt + 2, lbuf);
        cp_commit();

        const uint32_t aBaseH = sbase + (uint32_t)cbuf * STG_B;
        const uint32_t aBaseL = aBaseH + ABLK_B;
        const uint32_t bBase  = aBaseH + 2 * ABLK_B;

#pragma unroll
        for (int k16 = 0; k16 < 2; k16++) {
            uint32_t afh[FM][4], afl[FM][4];
            const int acol = k16 * 16 + ((lane >> 4) << 3);
#pragma unroll
            for (int fm = 0; fm < FM; fm++) {
                const int arow = wm * WTM + fm * 16 + (lane & 15);
                const uint32_t aoff = (uint32_t)(arow * LDS + acol) * 2u;
                ldsm4(afh[fm], aBaseH + aoff);
                ldsm4(afl[fm], aBaseL + aoff);
            }
            const int brlane = ((lane >> 4) << 3) + (lane & 7);
            const int bcol   = k16 * 16 + (((lane >> 3) & 1) << 3);
#pragma unroll
            for (int fn2 = 0; fn2 < FN / 2; fn2++) {
                const int brow = wn * WTN + fn2 * 16 + brlane;
                const uint32_t boff = (uint32_t)(brow * LDS + bcol) * 2u;
                uint32_t bh[4];
                ldsm4(bh, bBase + boff);
#pragma unroll
                for (int fm = 0; fm < FM; fm++) {
                    float* c0 = acc[fm][2 * fn2];
                    float* c1 = acc[fm][2 * fn2 + 1];
                    mma_f16(c0, afh[fm], bh[0], bh[1]);
                    mma_f16(c0, afl[fm], bh[0], bh[1]);
                    mma_f16(c1, afh[fm], bh[2], bh[3]);
                    mma_f16(c1, afl[fm], bh[2], bh[3]);
                }
            }
        }
        __syncthreads();
        cbuf = (cbuf == 2) ? 0 : cbuf + 1;
        lbuf = (lbuf == 2) ? 0 : lbuf + 1;
    }

    const int gid = lane >> 2, tig = lane & 3;
#pragma unroll
    for (int fm = 0; fm < FM; fm++) {
        const int m0 = bm + wm * WTM + fm * 16 + gid;
#pragma unroll
        for (int fn = 0; fn < FN; fn++) {
            const int n0 = bn + wn * WTN + fn * 8 + tig * 2;
            if (EPI == 2) {
                const int i = n0 >> 1;
                const float bm_ = g.bias[i], bs_ = g.bias[i + SDIM];
                float me0 = acc[fm][fn][0] + bm_;
                float sd0 = softplusf_(acc[fm][fn][1] + bs_) + 0.1f;
                float me1 = acc[fm][fn][2] + bm_;
                float sd1 = softplusf_(acc[fm][fn][3] + bs_) + 0.1f;
                const size_t o0 = (size_t)m0 * SDIM + i;
                const size_t o1 = (size_t)(m0 + 8) * SDIM + i;
                g.C [o0] = me0;  g.C [o1] = me1;
                g.C2[o0] = sd0;  g.C2[o1] = sd1;
                float s0 = fmaf(sd0, g.noise[o0], me0);
                float s1 = fmaf(sd1, g.noise[o1], me1);
                g.S[o0] = s0;  g.S[o1] = s1;
                if (g.Sh) {
                    float sc0 = s0 * g.ntNext[m0];
                    float sc1 = s1 * g.ntNext[m0 + 8];
                    half_t h, l;
                    split_h(sc0, h, l); g.Sh[o0] = h; g.Sl[o0] = l;
                    split_h(sc1, h, l); g.Sh[o1] = h; g.Sl[o1] = l;
                }
            } else if (EPI == 3) {
                if (n0 < NDIM) {
                    const float b0 = g.bias[n0], b1 = g.bias[n0 + 1];
                    float v00 = fmaxf(acc[fm][fn][0] + b0, 0.0f);
                    float v01 = fmaxf(acc[fm][fn][1] + b1, 0.0f);
                    float v10 = fmaxf(acc[fm][fn][2] + b0, 0.0f);
                    float v11 = fmaxf(acc[fm][fn][3] + b1, 0.0f);
                    half_t h0, l0, h1, l1;
                    split_h(v00, h0, l0); split_h(v01, h1, l1);
                    *reinterpret_cast<uint32_t*>(g.Ch + (size_t)m0 * NDIM + n0) = pack_h2(h0, h1);
                    *reinterpret_cast<uint32_t*>(g.Cl + (size_t)m0 * NDIM + n0) = pack_h2(l0, l1);
                    split_h(v10, h0, l0); split_h(v11, h1, l1);
                    *reinterpret_cast<uint32_t*>(g.Ch + (size_t)(m0 + 8) * NDIM + n0) = pack_h2(h0, h1);
                    *reinterpret_cast<uint32_t*>(g.Cl + (size_t)(m0 + 8) * NDIM + n0) = pack_h2(l0, l1);
                } else {
                    const int nq = n0 - NDIM;
                    float2 p0 = *reinterpret_cast<const float2*>(g.C + (size_t)m0 * NDIM + nq);
                    float2 p1 = *reinterpret_cast<const float2*>(g.C + (size_t)(m0 + 8) * NDIM + nq);
                    float v00 = fmaxf(acc[fm][fn][0] + p0.x, 0.0f);
                    float v01 = fmaxf(acc[fm][fn][1] + p0.y, 0.0f);
                    float v10 = fmaxf(acc[fm][fn][2] + p1.x, 0.0f);
                    float v11 = fmaxf(acc[fm][fn][3] + p1.y, 0.0f);
                    half_t h0, l0, h1, l1;
                    split_h(v00, h0, l0); split_h(v01, h1, l1);
                    *reinterpret_cast<uint32_t*>(g.Sh + (size_t)m0 * NDIM + nq) = pack_h2(h0, h1);
                    *reinterpret_cast<uint32_t*>(g.Sl + (size_t)m0 * NDIM + nq) = pack_h2(l0, l1);
                    split_h(v10, h0, l0); split_h(v11, h1, l1);
                    *reinterpret_cast<uint32_t*>(g.Sh + (size_t)(m0 + 8) * NDIM + nq) = pack_h2(h0, h1);
                    *reinterpret_cast<uint32_t*>(g.Sl + (size_t)(m0 + 8) * NDIM + nq) = pack_h2(l0, l1);
                }
            } else {
                const float b0 = g.bias[n0], b1 = g.bias[n0 + 1];
                float v00 = acc[fm][fn][0] + b0, v01 = acc[fm][fn][1] + b1;
                float v10 = acc[fm][fn][2] + b0, v11 = acc[fm][fn][3] + b1;
                if (EPI == 1) {
                    v00 = fmaxf(v00, 0.0f); v01 = fmaxf(v01, 0.0f);
                    v10 = fmaxf(v10, 0.0f); v11 = fmaxf(v11, 0.0f);
                    half_t h0, l0, h1, l1;
                    split_h(v00, h0, l0); split_h(v01, h1, l1);
                    *reinterpret_cast<uint32_t*>(g.Ch + (size_t)m0 * N + n0) = pack_h2(h0, h1);
                    *reinterpret_cast<uint32_t*>(g.Cl + (size_t)m0 * N + n0) = pack_h2(l0, l1);
                    split_h(v10, h0, l0); split_h(v11, h1, l1);
                    *reinterpret_cast<uint32_t*>(g.Ch + (size_t)(m0 + 8) * N + n0) = pack_h2(h0, h1);
                    *reinterpret_cast<uint32_t*>(g.Cl + (size_t)(m0 + 8) * N + n0) = pack_h2(l0, l1);
                } else {
                    *reinterpret_cast<float2*>(g.C + (size_t)m0 * N + n0)       = make_float2(v00, v01);
                    *reinterpret_cast<float2*>(g.C + (size_t)(m0 + 8) * N + n0) = make_float2(v10, v11);
                }
            }
        }
    }
}

// ---------------- GRU gates + h split ----------------------------------------
__global__ void gru_gate_kernel(const float* __restrict__ hprev, float* __restrict__ hnew,
                                half_t* __restrict__ hh, half_t* __restrict__ hl)
{
    const int H4 = HDIM / 4;
    int idx = blockIdx.x * blockDim.x + threadIdx.x;
    if (idx >= BDIM * H4) return;
    int m = idx / H4, j4 = idx % H4;
    const float4* gi = reinterpret_cast<const float4*>(g_gi + (size_t)m * 3 * HDIM);
    const float4* gh = reinterpret_cast<const float4*>(g_gh + (size_t)m * 3 * HDIM);
    float4 ir = gi[j4], iz = gi[j4 + H4], in_ = gi[j4 + 2 * H4];
    float4 hr = gh[j4], hz = gh[j4 + H4], hn = gh[j4 + 2 * H4];
    float4 hp = reinterpret_cast<const float4*>(hprev + (size_t)m * HDIM)[j4];
    float4 o;
    { float r = sigmoidf_(ir.x + hr.x), z = sigmoidf_(iz.x + hz.x);
      float n = tanhf_(in_.x + r * hn.x); o.x = (1.0f - z) * n + z * hp.x; }
    { float r = sigmoidf_(ir.y + hr.y), z = sigmoidf_(iz.y + hz.y);
      float n = tanhf_(in_.y + r * hn.y); o.y = (1.0f - z) * n + z * hp.y; }
    { float r = sigmoidf_(ir.z + hr.z), z = sigmoidf_(iz.z + hz.z);
      float n = tanhf_(in_.z + r * hn.z); o.z = (1.0f - z) * n + z * hp.z; }
    { float r = sigmoidf_(ir.w + hr.w), z = sigmoidf_(iz.w + hz.w);
      float n = tanhf_(in_.w + r * hn.w); o.w = (1.0f - z) * n + z * hp.w; }
    reinterpret_cast<float4*>(hnew)[idx] = o;
    split_store4(o, hh, hl, idx);
}

// ------------------------------- launch --------------------------------------
extern "C" void kernel_launch(void* const* d_in, const int* in_sizes, int n_in,
                              void* d_out, int out_size)
{
    (void)in_sizes; (void)n_in; (void)out_size;
    const float* prev_hidden = (const float*)d_in[0];
    const float* prev_state  = (const float*)d_in[1];
    const float* actions     = (const float*)d_in[2];
    const float* obs         = (const float*)d_in[3];
    const float* non_terms   = (const float*)d_in[4];
    const float* prior_noise = (const float*)d_in[5];
    const float* post_noise  = (const float*)d_in[6];
    const float* W_sa = (const float*)d_in[7];
    const float* b_sa = (const float*)d_in[8];
    const float* W_ih = (const float*)d_in[9];
    const float* W_hh = (const float*)d_in[10];
    const float* b_ih = (const float*)d_in[11];
    const float* b_hh = (const float*)d_in[12];
    const float* W_ep = (const float*)d_in[13];
    const float* b_ep = (const float*)d_in[14];
    const float* W_pr = (const float*)d_in[15];
    const float* b_pr = (const float*)d_in[16];
    const float* W_eq = (const float*)d_in[17];
    const float* b_eq = (const float*)d_in[18];
    const float* W_po = (const float*)d_in[19];
    const float* b_po = (const float*)d_in[20];

    float* out = (float*)d_out;
    const size_t off_pm     = LBH;
    const size_t off_ps     = LBH + 1 * LBS;
    const size_t off_sprior = LBH + 2 * LBS;
    const size_t off_qm     = LBH + 3 * LBS;
    const size_t off_qs     = LBH + 4 * LBS;
    const size_t off_spost  = LBH + 5 * LBS;

    float *gi, *gh, *qp;
    cudaGetSymbolAddress((void**)&gi, g_gi);
    cudaGetSymbolAddress((void**)&gh, g_gh);
    cudaGetSymbolAddress((void**)&qp, g_qp);
    half_t *x_h, *x_l, *h_h, *h_l, *pe_h, *pe_l, *qe_h, *qe_l, *ob_h, *ob_l;
    half_t *sp_h, *sp_l, *act_h, *act_l;
    cudaGetSymbolAddress((void**)&x_h,  g_x_h);  cudaGetSymbolAddress((void**)&x_l,  g_x_l);
    cudaGetSymbolAddress((void**)&h_h,  g_h_h);  cudaGetSymbolAddress((void**)&h_l,  g_h_l);
    cudaGetSymbolAddress((void**)&pe_h, g_pe_h); cudaGetSymbolAddress((void**)&pe_l, g_pe_l);
    cudaGetSymbolAddress((void**)&qe_h, g_qe_h); cudaGetSymbolAddress((void**)&qe_l, g_qe_l);
    cudaGetSymbolAddress((void**)&ob_h, g_ob_h); cudaGetSymbolAddress((void**)&ob_l, g_ob_l);
    cudaGetSymbolAddress((void**)&sp_h, g_sp_h); cudaGetSymbolAddress((void**)&sp_l, g_sp_l);
    cudaGetSymbolAddress((void**)&act_h, g_act_h); cudaGetSymbolAddress((void**)&act_l, g_act_l);

    half_t *Wsa, *Wih, *Whh, *Wpq, *Wq2, *Wpr, *Wpo;
    cudaGetSymbolAddress((void**)&Wsa, g_Wsa);
    cudaGetSymbolAddress((void**)&Wih, g_Wih);
    cudaGetSymbolAddress((void**)&Whh, g_Whh);
    cudaGetSymbolAddress((void**)&Wpq, g_Wpq);
    cudaGetSymbolAddress((void**)&Wq2, g_Wq2);
    cudaGetSymbolAddress((void**)&Wpr, g_Wpr);
    cudaGetSymbolAddress((void**)&Wpo, g_Wpo);

    // ---- dynamic smem ----
    const int SM_BIG  = 3 * (2 * 128 * 40 + 96 * 40) * 2;    // 84480 (2 CTAs/SM)
    const int SM_PQ   = 3 * (2 * 64 * 40 + 128 * 40) * 2;    // 61440 (batched qp)
    const int SM_X    = 3 * (2 * 64 * 40 + 64 * 40) * 2;     // 46080
    const int SM_HEAD = 3 * (2 * 32 * 40 + 64 * 40) * 2;     // 30720
    cudaFuncSetAttribute((const void*)gemm_tc<128, 96, 4, 2, 8, 0, 2>,
                         cudaFuncAttributeMaxDynamicSharedMemorySize, SM_BIG);
    cudaFuncSetAttribute((const void*)gemm_tc<64, 128, 2, 4, 8, 0, 1>,
                         cudaFuncAttributeMaxDynamicSharedMemorySize, SM_PQ);
    cudaFuncSetAttribute((const void*)gemm_tc<64, 64, 2, 4, 8, 3, 2>,
                         cudaFuncAttributeMaxDynamicSharedMemorySize, SM_X);
    cudaFuncSetAttribute((const void*)gemm_tc<64, 64, 2, 4, 8, 1, 1>,
                         cudaFuncAttributeMaxDynamicSharedMemorySize, SM_X);
    cudaFuncSetAttribute((const void*)gemm_tc<32, 64, 1, 4, 4, 2, 1>,
                         cudaFuncAttributeMaxDynamicSharedMemorySize, SM_HEAD);

    // ---- launch 0: one-shot prep ----
    prep_kernel<<<N_TOT / 256, 256>>>(
        W_ih, W_hh, W_sa, W_ep, W_eq, W_pr, W_po,
        prev_hidden, prev_state, non_terms, actions, obs,
        Wih, Whh, Wsa, Wpq, Wq2, Wpr, Wpo,
        h_h, h_l, sp_h, sp_l, act_h, act_l, ob_h, ob_l);

    // ---- launch 1: batched qe obs-partial ----
    {
        G a{ob_h, ob_l, ob_h, ob_l, Wq2, b_eq, qp, nullptr, nullptr, nullptr,
            nullptr, nullptr, nullptr, nullptr, nullptr, EDIM, EDIM, EDIM, EDIM};
        gemm_tc<64, 128, 2, 4, 8, 0, 1><<<dim3(NDIM / 128, LSTEPS * BDIM / 64, 1), 256, SM_PQ>>>(
            a, a, NDIM);
    }

    const int KSA = SDIM + ADIM;

    for (int t = 0; t < LSTEPS; t++) {
        const float* hprev = (t == 0) ? prev_hidden : out + (size_t)(t - 1) * BH;
        float* hnew = out + (size_t)t * BH;
        const half_t* act_ht = act_h + (size_t)t * BDIM * ADIM;
        const half_t* act_lt = act_l + (size_t)t * BDIM * ADIM;
        const float* ntNext = non_terms + (size_t)((t + 1 < LSTEPS) ? t + 1 : t) * BDIM;
        float* qp_t = qp + (size_t)t * BDIM * NDIM;

        // x = relu([spost*nt, a] @ Wsa^T + b_sa)
        {
            G a{sp_h, sp_l, act_ht, act_lt, Wsa, b_sa,
                nullptr, nullptr, nullptr, nullptr, x_h, x_l,
                nullptr, nullptr, nullptr, KSA, SDIM, SDIM, ADIM};
            gemm_tc<64, 64, 2, 4, 8, 1, 1><<<dim3(HDIM / 64, BDIM / 64, 1), 256, SM_X>>>(
                a, a, HDIM);
        }
        // gi/gh big GEMM: 256 CTAs (2 waves), 2 CTAs/SM   (idx 3 at t=0 -> profiled)
        {
            G a0{x_h, x_l, x_h, x_l, Wih, b_ih, gi, nullptr, nullptr, nullptr,
                 nullptr, nullptr, nullptr, nullptr, nullptr, HDIM, HDIM, HDIM, HDIM};
            G a1{h_h, h_l, h_h, h_l, Whh, b_hh, gh, nullptr, nullptr, nullptr,
                 nullptr, nullptr, nullptr, nullptr, nullptr, HDIM, HDIM, HDIM, HDIM};
            gemm_tc<128, 96, 4, 2, 8, 0, 2><<<dim3(3 * HDIM / 96, BDIM / 128, 2), 256, SM_BIG>>>(
                a0, a1, 3 * HDIM);
        }
        // GRU gates -> hnew fp32 + h hi/lo
        gru_gate_kernel<<<(int)(BH / 4 / 256), 256>>>(hprev, hnew, h_h, h_l);

        // merged pe|qe: virtual N=2048, K=1024, 256 CTAs, 2+ CTAs/SM
        {
            G a{h_h, h_l, h_h, h_l, Wpq, b_ep, qp_t, nullptr, nullptr, nullptr,
                pe_h, pe_l, qe_h, qe_l, nullptr, HDIM, HDIM, HDIM, HDIM};
            gemm_tc<64, 64, 2, 4, 8, 3, 2><<<dim3(2 * NDIM / 64, BDIM / 64, 1), 256, SM_X>>>(
                a, a, 2 * NDIM);
        }
        // heads + reparameterized states
        float* pm_o = out + off_pm + (size_t)t * BS;
        float* ps_o = out + off_ps + (size_t)t * BS;
        float* qm_o = out + off_qm + (size_t)t * BS;
        float* qs_o = out + off_qs + (size_t)t * BS;
        {
            G a0{pe_h, pe_l, pe_h, pe_l, Wpr, b_pr, pm_o, ps_o,
                 prior_noise + (size_t)t * BS, out + off_sprior + (size_t)t * BS,
                 nullptr, nullptr, nullptr, nullptr, nullptr, NDIM, NDIM, NDIM, NDIM};
            G a1{qe_h, qe_l, qe_h, qe_l, Wpo, b_po, qm_o, qs_o,
                 post_noise + (size_t)t * BS, out + off_spost + (size_t)t * BS,
                 nullptr, nullptr, sp_h, sp_l, ntNext, NDIM, NDIM, NDIM, NDIM};
            gemm_tc<32, 64, 1, 4, 4, 2, 1><<<dim3(2 * SDIM / 64, BDIM / 32, 2), 128, SM_HEAD>>>(
                a0, a1, 2 * SDIM);
        }
    }
}